// round 1
// baseline (speedup 1.0000x reference)
#include <cuda_runtime.h>
#include <cstddef>

#define Nn   131072
#define Ee   524288
#define Gg   4096
#define DIN  128
#define DH   512
#define DOUT 256
#define BN_EPS 1e-5f

// ---------------- scratch (device globals: allocation-free rule) ----------------
__device__ float g_deg [Nn];
__device__ float g_dinv[Nn];
__device__ float g_hw  [(size_t)Nn * DH];   // GEMM output h@W
__device__ float g_agg [(size_t)Nn * DH];   // aggregated (scatter) output
__device__ float g_act [(size_t)Nn * DH];   // bn(relu(.)) output
__device__ float g_pool[Gg * DOUT];
__device__ float g_tmp [Gg * DOUT];

// ---------------- degree / norm ----------------
__global__ void deg_init_k(float* deg) {
    int i = blockIdx.x * blockDim.x + threadIdx.x;
    if (i < Nn) deg[i] = 1.0f;                       // self loop
}
__global__ void deg_acc_k(const int* __restrict__ dst, float* deg) {
    int e = blockIdx.x * blockDim.x + threadIdx.x;
    if (e < Ee) atomicAdd(&deg[dst[e]], 1.0f);
}
__global__ void dinv_k(const float* __restrict__ deg, float* dinv) {
    int i = blockIdx.x * blockDim.x + threadIdx.x;
    if (i < Nn) dinv[i] = rsqrtf(deg[i]);            // deg >= 1 always
}

// ---------------- SGEMM: C[M,Nd] = A[M,K] @ B[K,Nd]  (all dims % 128/16 == 0) ----------------
// EPI: 0 = plain, 1 = +bias +relu, 2 = +bias
template <int EPI>
__global__ __launch_bounds__(256) void sgemm_k(
    const float* __restrict__ A, const float* __restrict__ B,
    const float* __restrict__ bias, float* __restrict__ C,
    int M, int K, int Nd)
{
    __shared__ float As[16][128];
    __shared__ float Bs[16][128];
    const int tid = threadIdx.x;
    const int bx = blockIdx.x, by = blockIdx.y;
    const int tx = tid & 15, ty = tid >> 4;

    const float* Ablk = A + (size_t)by * 128 * K;
    const float* Bblk = B + bx * 128;

    const int arow = tid >> 2;            // 0..63
    const int acol = (tid & 3) * 4;       // 0,4,8,12
    const int brow = tid >> 5;            // 0..7
    const int bcol = (tid & 31) * 4;      // 0..124

    float acc[8][8];
    #pragma unroll
    for (int i = 0; i < 8; i++)
        #pragma unroll
        for (int j = 0; j < 8; j++) acc[i][j] = 0.f;

    for (int k0 = 0; k0 < K; k0 += 16) {
        #pragma unroll
        for (int i = 0; i < 2; i++) {
            int r = arow + 64 * i;
            float4 v = *(const float4*)(Ablk + (size_t)r * K + k0 + acol);
            As[acol + 0][r] = v.x;
            As[acol + 1][r] = v.y;
            As[acol + 2][r] = v.z;
            As[acol + 3][r] = v.w;
        }
        #pragma unroll
        for (int i = 0; i < 2; i++) {
            int kr = brow + 8 * i;
            float4 v = *(const float4*)(Bblk + (size_t)(k0 + kr) * Nd + bcol);
            *(float4*)&Bs[kr][bcol] = v;
        }
        __syncthreads();
        #pragma unroll
        for (int kk = 0; kk < 16; kk++) {
            float ra[8], rb[8];
            #pragma unroll
            for (int i = 0; i < 8; i++) ra[i] = As[kk][ty * 8 + i];
            #pragma unroll
            for (int j = 0; j < 8; j++) rb[j] = Bs[kk][tx * 8 + j];
            #pragma unroll
            for (int i = 0; i < 8; i++)
                #pragma unroll
                for (int j = 0; j < 8; j++)
                    acc[i][j] += ra[i] * rb[j];
        }
        __syncthreads();
    }

    float* Cblk = C + (size_t)by * 128 * Nd + bx * 128;
    #pragma unroll
    for (int i = 0; i < 8; i++) {
        int row = ty * 8 + i;
        #pragma unroll
        for (int j = 0; j < 8; j += 4) {
            float4 v;
            v.x = acc[i][j + 0]; v.y = acc[i][j + 1];
            v.z = acc[i][j + 2]; v.w = acc[i][j + 3];
            if (EPI >= 1) {
                int col = bx * 128 + tx * 8 + j;
                v.x += bias[col + 0]; v.y += bias[col + 1];
                v.z += bias[col + 2]; v.w += bias[col + 3];
                if (EPI == 1) {
                    v.x = fmaxf(v.x, 0.f); v.y = fmaxf(v.y, 0.f);
                    v.z = fmaxf(v.z, 0.f); v.w = fmaxf(v.w, 0.f);
                }
            }
            *(float4*)(Cblk + (size_t)row * Nd + tx * 8 + j) = v;
        }
    }
}

// ---------------- aggregation ----------------
// agg[i,:] = bias + hw[i,:] * dinv[i]^2     (self-loop term + bias)
__global__ void agg_init_k(const float4* __restrict__ hw, const float* __restrict__ bias,
                           const float* __restrict__ dinv, float4* __restrict__ agg,
                           int q /*Nd/4*/, int total4)
{
    int idx = blockIdx.x * blockDim.x + threadIdx.x;
    if (idx >= total4) return;
    int node = idx / q;
    int c4 = (idx - node * q) * 4;
    float s = dinv[node]; s *= s;
    float4 v = hw[idx];
    v.x = v.x * s + bias[c4 + 0];
    v.y = v.y * s + bias[c4 + 1];
    v.z = v.z * s + bias[c4 + 2];
    v.w = v.w * s + bias[c4 + 3];
    agg[idx] = v;
}

__device__ __forceinline__ void red_add_v4(float* addr, float4 v) {
    asm volatile("red.global.add.v4.f32 [%0], {%1,%2,%3,%4};"
                 :: "l"(addr), "f"(v.x), "f"(v.y), "f"(v.z), "f"(v.w) : "memory");
}

// one warp per edge: agg[dst,:] += hw[src,:] * dinv[src]*dinv[dst]
__global__ void scatter_k(const int* __restrict__ src, const int* __restrict__ dst,
                          const float* __restrict__ dinv, const float* __restrict__ hw,
                          float* __restrict__ agg, int Nd)
{
    int w = (blockIdx.x * blockDim.x + threadIdx.x) >> 5;
    int lane = threadIdx.x & 31;
    if (w >= Ee) return;
    int s = src[w], d = dst[w];
    float c = dinv[s] * dinv[d];
    const float4* hp = (const float4*)(hw + (size_t)s * Nd);
    float* ap = agg + (size_t)d * Nd;
    int q = Nd >> 2;
    for (int j = lane; j < q; j += 32) {
        float4 v = hp[j];
        v.x *= c; v.y *= c; v.z *= c; v.w *= c;
        red_add_v4(ap + j * 4, v);
    }
}

// ---------------- bn(relu(h)) elementwise ----------------
__global__ void bnrelu_k(const float4* __restrict__ in,
                         const float* __restrict__ g, const float* __restrict__ be,
                         const float* __restrict__ m, const float* __restrict__ v,
                         float4* __restrict__ out, int q /*Nd/4*/, int total4)
{
    int idx = blockIdx.x * blockDim.x + threadIdx.x;
    if (idx >= total4) return;
    int node = idx / q;
    int c4 = (idx - node * q) * 4;
    float4 h = in[idx];
    float4 r;
    r.x = g[c4 + 0] * rsqrtf(v[c4 + 0] + BN_EPS) * (fmaxf(h.x, 0.f) - m[c4 + 0]) + be[c4 + 0];
    r.y = g[c4 + 1] * rsqrtf(v[c4 + 1] + BN_EPS) * (fmaxf(h.y, 0.f) - m[c4 + 1]) + be[c4 + 1];
    r.z = g[c4 + 2] * rsqrtf(v[c4 + 2] + BN_EPS) * (fmaxf(h.z, 0.f) - m[c4 + 2]) + be[c4 + 2];
    r.w = g[c4 + 3] * rsqrtf(v[c4 + 3] + BN_EPS) * (fmaxf(h.w, 0.f) - m[c4 + 3]) + be[c4 + 3];
    out[idx] = r;
}

// ---------------- mean pool by sorted batch: one block per graph ----------------
__device__ __forceinline__ int lower_bound_i(const int* a, int n, int key) {
    int lo = 0, hi = n;
    while (lo < hi) { int mid = (lo + hi) >> 1; if (a[mid] < key) lo = mid + 1; else hi = mid; }
    return lo;
}
__global__ void pool_k(const float* __restrict__ h, const int* __restrict__ batch,
                       float* __restrict__ pooled)
{
    int gph = blockIdx.x;
    __shared__ int s_lo, s_hi;
    if (threadIdx.x == 0) {
        s_lo = lower_bound_i(batch, Nn, gph);
        s_hi = lower_bound_i(batch, Nn, gph + 1);
    }
    __syncthreads();
    int lo = s_lo, hi = s_hi;
    int c = threadIdx.x;                 // DOUT threads
    float acc = 0.f;
    for (int i = lo; i < hi; i++) acc += h[(size_t)i * DOUT + c];
    float cnt = (float)((hi - lo) > 0 ? (hi - lo) : 1);
    pooled[gph * DOUT + c] = acc / cnt;
}

// ---------------- launch ----------------
extern "C" void kernel_launch(void* const* d_in, const int* in_sizes, int n_in,
                              void* d_out, int out_size)
{
    const float* x   = (const float*)d_in[0];
    const int*   ei  = (const int*)  d_in[1];
    const int*   bat = (const int*)  d_in[2];
    const float* W1  = (const float*)d_in[3];
    const float* b1  = (const float*)d_in[4];
    const float* W2  = (const float*)d_in[5];
    const float* b2  = (const float*)d_in[6];
    const float* W3  = (const float*)d_in[7];
    const float* b3  = (const float*)d_in[8];
    const float* g1  = (const float*)d_in[9];
    const float* be1 = (const float*)d_in[10];
    const float* m1  = (const float*)d_in[11];
    const float* v1  = (const float*)d_in[12];
    const float* g2  = (const float*)d_in[13];
    const float* be2 = (const float*)d_in[14];
    const float* m2  = (const float*)d_in[15];
    const float* v2  = (const float*)d_in[16];
    const float* g3  = (const float*)d_in[17];
    const float* be3 = (const float*)d_in[18];
    const float* m3  = (const float*)d_in[19];
    const float* v3  = (const float*)d_in[20];
    const float* Wf1 = (const float*)d_in[21];
    const float* bf1 = (const float*)d_in[22];
    const float* Wf2 = (const float*)d_in[23];
    const float* bf2 = (const float*)d_in[24];

    const int* src = ei;
    const int* dst = ei + Ee;

    float *p_deg, *p_dinv, *p_hw, *p_agg, *p_act, *p_pool, *p_tmp;
    cudaGetSymbolAddress((void**)&p_deg,  g_deg);
    cudaGetSymbolAddress((void**)&p_dinv, g_dinv);
    cudaGetSymbolAddress((void**)&p_hw,   g_hw);
    cudaGetSymbolAddress((void**)&p_agg,  g_agg);
    cudaGetSymbolAddress((void**)&p_act,  g_act);
    cudaGetSymbolAddress((void**)&p_pool, g_pool);
    cudaGetSymbolAddress((void**)&p_tmp,  g_tmp);

    // degree / normalization
    deg_init_k<<<Nn / 256, 256>>>(p_deg);
    deg_acc_k <<<Ee / 256, 256>>>(dst, p_deg);
    dinv_k    <<<Nn / 256, 256>>>(p_deg, p_dinv);

    const int t4_DH   = Nn * DH / 4;     // 16,777,216
    const int t4_DOUT = Nn * DOUT / 4;   //  8,388,608
    const int scat_blocks = (Ee * 32) / 256;

    // ---- layer 1: 128 -> 512 ----
    sgemm_k<0><<<dim3(DH / 128, Nn / 128), 256>>>(x, W1, nullptr, p_hw, Nn, DIN, DH);
    agg_init_k<<<t4_DH / 256, 256>>>((const float4*)p_hw, b1, p_dinv, (float4*)p_agg, DH / 4, t4_DH);
    scatter_k<<<scat_blocks, 256>>>(src, dst, p_dinv, p_hw, p_agg, DH);
    bnrelu_k<<<t4_DH / 256, 256>>>((const float4*)p_agg, g1, be1, m1, v1, (float4*)p_act, DH / 4, t4_DH);

    // ---- layer 2: 512 -> 512 ----
    sgemm_k<0><<<dim3(DH / 128, Nn / 128), 256>>>(p_act, W2, nullptr, p_hw, Nn, DH, DH);
    agg_init_k<<<t4_DH / 256, 256>>>((const float4*)p_hw, b2, p_dinv, (float4*)p_agg, DH / 4, t4_DH);
    scatter_k<<<scat_blocks, 256>>>(src, dst, p_dinv, p_hw, p_agg, DH);
    bnrelu_k<<<t4_DH / 256, 256>>>((const float4*)p_agg, g2, be2, m2, v2, (float4*)p_act, DH / 4, t4_DH);

    // ---- layer 3: 512 -> 256 ----
    sgemm_k<0><<<dim3(DOUT / 128, Nn / 128), 256>>>(p_act, W3, nullptr, p_hw, Nn, DH, DOUT);
    agg_init_k<<<t4_DOUT / 256, 256>>>((const float4*)p_hw, b3, p_dinv, (float4*)p_agg, DOUT / 4, t4_DOUT);
    scatter_k<<<scat_blocks, 256>>>(src, dst, p_dinv, p_hw, p_agg, DOUT);
    bnrelu_k<<<t4_DOUT / 256, 256>>>((const float4*)p_agg, g3, be3, m3, v3, (float4*)p_act, DOUT / 4, t4_DOUT);

    // ---- pool + MLP head ----
    pool_k<<<Gg, DOUT>>>(p_act, bat, p_pool);
    sgemm_k<1><<<dim3(DOUT / 128, Gg / 128), 256>>>(p_pool, Wf1, bf1, p_tmp, Gg, DOUT, DOUT);
    sgemm_k<2><<<dim3(DOUT / 128, Gg / 128), 256>>>(p_tmp, Wf2, bf2, (float*)d_out, Gg, DOUT, DOUT);
}

// round 2
// speedup vs baseline: 1.2977x; 1.2977x over previous
#include <cuda_runtime.h>
#include <cstddef>

#define Nn   131072
#define Ee   524288
#define Gg   4096
#define DIN  128
#define DH   512
#define DOUT 256
#define BN_EPS 1e-5f

// ---------------- scratch (device globals: allocation-free rule) ----------------
__device__ float g_deg [Nn];
__device__ float g_dinv[Nn];
__device__ float g_hs  [(size_t)Nn * DH];   // (h@W) * dinv[row]
__device__ float g_acc [(size_t)Nn * DH];   // scatter accumulator (init = hs)
__device__ float g_act [(size_t)Nn * DH];   // bn(relu(.)) output
__device__ float g_pool[Gg * DOUT];
__device__ float g_tmp [Gg * DOUT];

// ---------------- degree / norm ----------------
__global__ void deg_init_k(float* deg) {
    int i = blockIdx.x * blockDim.x + threadIdx.x;
    if (i < Nn) deg[i] = 1.0f;                       // self loop
}
__global__ void deg_acc_k(const int* __restrict__ dst, float* deg) {
    int e = blockIdx.x * blockDim.x + threadIdx.x;
    if (e < Ee) atomicAdd(&deg[dst[e]], 1.0f);
}
__global__ void dinv_k(const float* __restrict__ deg, float* dinv) {
    int i = blockIdx.x * blockDim.x + threadIdx.x;
    if (i < Nn) dinv[i] = rsqrtf(deg[i]);
}

// ---------------- tf32 helpers ----------------
__device__ __forceinline__ float to_tf32(float x) {
    unsigned u;
    asm("cvt.rna.tf32.f32 %0, %1;" : "=r"(u) : "f"(x));
    return __uint_as_float(u);
}
__device__ __forceinline__ void mma_tf32(float* d, const float* a, const float* b) {
    asm volatile(
        "mma.sync.aligned.m16n8k8.row.col.f32.tf32.tf32.f32 "
        "{%0,%1,%2,%3}, {%4,%5,%6,%7}, {%8,%9}, {%0,%1,%2,%3};"
        : "+f"(d[0]), "+f"(d[1]), "+f"(d[2]), "+f"(d[3])
        : "r"(__float_as_uint(a[0])), "r"(__float_as_uint(a[1])),
          "r"(__float_as_uint(a[2])), "r"(__float_as_uint(a[3])),
          "r"(__float_as_uint(b[0])), "r"(__float_as_uint(b[1])));
}

// ---------------- tf32 tensor-core GEMM: C[M,Nd] = A[M,K] @ B[K,Nd] ----------------
// Block tile 128x128, BK=32, 256 threads = 8 warps (4M x 2N), warp tile 32x64.
// EPI: 0 plain | 1 +bias+relu | 2 +bias | 3 GCN: scale by dinv[row], dual-store C and C2
template <int EPI>
__global__ __launch_bounds__(256) void tgemm_k(
    const float* __restrict__ A, const float* __restrict__ B,
    const float* __restrict__ bias, const float* __restrict__ dinv,
    float* __restrict__ C, float* __restrict__ C2,
    int M, int K, int Nd)
{
    __shared__ float As[128][33];   // [m][k] padded
    __shared__ float Bs[32][129];   // [k][n] padded

    const int tid  = threadIdx.x;
    const int warp = tid >> 5, lane = tid & 31;
    const int wm = (warp >> 1) * 32;     // warp M offset (4 warps)
    const int wn = (warp & 1) * 64;      // warp N offset (2 warps)
    const int grp = lane >> 2, qid = lane & 3;

    const size_t row0 = (size_t)blockIdx.y * 128;
    const float* Ablk = A + row0 * K;
    const float* Bblk = B + blockIdx.x * 128;

    float acc[2][8][4];
    #pragma unroll
    for (int i = 0; i < 2; i++)
        #pragma unroll
        for (int j = 0; j < 8; j++)
            #pragma unroll
            for (int l = 0; l < 4; l++) acc[i][j][l] = 0.f;

    const int ar = tid >> 3;            // 0..31  (A tile row group)
    const int ac = (tid & 7) * 4;       // 0..28
    const int br = tid >> 5;            // 0..7   (B tile k group)
    const int bc = (tid & 31) * 4;      // 0..124

    for (int k0 = 0; k0 < K; k0 += 32) {
        #pragma unroll
        for (int i = 0; i < 4; i++) {
            int r = ar + 32 * i;
            float4 v = *(const float4*)(Ablk + (size_t)r * K + k0 + ac);
            As[r][ac + 0] = to_tf32(v.x);
            As[r][ac + 1] = to_tf32(v.y);
            As[r][ac + 2] = to_tf32(v.z);
            As[r][ac + 3] = to_tf32(v.w);
        }
        #pragma unroll
        for (int i = 0; i < 4; i++) {
            int kr = br + 8 * i;
            float4 v = *(const float4*)(Bblk + (size_t)(k0 + kr) * Nd + bc);
            Bs[kr][bc + 0] = to_tf32(v.x);
            Bs[kr][bc + 1] = to_tf32(v.y);
            Bs[kr][bc + 2] = to_tf32(v.z);
            Bs[kr][bc + 3] = to_tf32(v.w);
        }
        __syncthreads();

        #pragma unroll
        for (int ks = 0; ks < 4; ks++) {
            const int kb = ks * 8;
            float a[2][4], b[8][2];
            #pragma unroll
            for (int mt = 0; mt < 2; mt++) {
                int r = wm + mt * 16 + grp;
                a[mt][0] = As[r    ][kb + qid];
                a[mt][1] = As[r + 8][kb + qid];
                a[mt][2] = As[r    ][kb + qid + 4];
                a[mt][3] = As[r + 8][kb + qid + 4];
            }
            #pragma unroll
            for (int nt = 0; nt < 8; nt++) {
                int n = wn + nt * 8 + grp;
                b[nt][0] = Bs[kb + qid    ][n];
                b[nt][1] = Bs[kb + qid + 4][n];
            }
            #pragma unroll
            for (int mt = 0; mt < 2; mt++)
                #pragma unroll
                for (int nt = 0; nt < 8; nt++)
                    mma_tf32(acc[mt][nt], a[mt], b[nt]);
        }
        __syncthreads();
    }

    // epilogue
    #pragma unroll
    for (int mt = 0; mt < 2; mt++) {
        const int gr0 = (int)row0 + wm + mt * 16 + grp;   // and gr0+8
        float s0 = 1.f, s1 = 1.f;
        if (EPI == 3) { s0 = dinv[gr0]; s1 = dinv[gr0 + 8]; }
        #pragma unroll
        for (int nt = 0; nt < 8; nt++) {
            int gc = blockIdx.x * 128 + wn + nt * 8 + 2 * qid;
            float2 v0, v1;
            v0.x = acc[mt][nt][0]; v0.y = acc[mt][nt][1];
            v1.x = acc[mt][nt][2]; v1.y = acc[mt][nt][3];
            if (EPI == 3) { v0.x *= s0; v0.y *= s0; v1.x *= s1; v1.y *= s1; }
            if (EPI == 1 || EPI == 2) {
                float bx = bias[gc], by = bias[gc + 1];
                v0.x += bx; v0.y += by; v1.x += bx; v1.y += by;
                if (EPI == 1) {
                    v0.x = fmaxf(v0.x, 0.f); v0.y = fmaxf(v0.y, 0.f);
                    v1.x = fmaxf(v1.x, 0.f); v1.y = fmaxf(v1.y, 0.f);
                }
            }
            *(float2*)(C + (size_t)gr0 * Nd + gc)       = v0;
            *(float2*)(C + (size_t)(gr0 + 8) * Nd + gc) = v1;
            if (EPI == 3) {
                *(float2*)(C2 + (size_t)gr0 * Nd + gc)       = v0;
                *(float2*)(C2 + (size_t)(gr0 + 8) * Nd + gc) = v1;
            }
        }
    }
}

// ---------------- scatter: acc[dst,:] += hs[src,:]  (pure, no scaling) ----------------
__device__ __forceinline__ void red_add_v4(float* addr, float4 v) {
    asm volatile("red.global.add.v4.f32 [%0], {%1,%2,%3,%4};"
                 :: "l"(addr), "f"(v.x), "f"(v.y), "f"(v.z), "f"(v.w) : "memory");
}
__global__ void scatter_k(const int* __restrict__ src, const int* __restrict__ dst,
                          const float* __restrict__ hs, float* __restrict__ acc, int Nd)
{
    int w = (blockIdx.x * blockDim.x + threadIdx.x) >> 5;
    int lane = threadIdx.x & 31;
    if (w >= Ee) return;
    int s = src[w], d = dst[w];
    const float4* hp = (const float4*)(hs + (size_t)s * Nd);
    float* ap = acc + (size_t)d * Nd;
    int q = Nd >> 2;
    for (int j = lane; j < q; j += 32)
        red_add_v4(ap + j * 4, hp[j]);
}

// ---------------- act = bn(relu(dinv[node]*acc + b)) ----------------
__global__ void bnrelu_k(const float4* __restrict__ in, const float* __restrict__ dinv,
                         const float* __restrict__ b,
                         const float* __restrict__ g, const float* __restrict__ be,
                         const float* __restrict__ m, const float* __restrict__ v,
                         float4* __restrict__ out, int q /*Nd/4*/, int total4)
{
    int idx = blockIdx.x * blockDim.x + threadIdx.x;
    if (idx >= total4) return;
    int node = idx / q;
    int c4 = (idx - node * q) * 4;
    float dv = dinv[node];
    float4 h = in[idx];
    float4 r;
    float y;
    y = fmaxf(dv * h.x + b[c4 + 0], 0.f);
    r.x = g[c4 + 0] * rsqrtf(v[c4 + 0] + BN_EPS) * (y - m[c4 + 0]) + be[c4 + 0];
    y = fmaxf(dv * h.y + b[c4 + 1], 0.f);
    r.y = g[c4 + 1] * rsqrtf(v[c4 + 1] + BN_EPS) * (y - m[c4 + 1]) + be[c4 + 1];
    y = fmaxf(dv * h.z + b[c4 + 2], 0.f);
    r.z = g[c4 + 2] * rsqrtf(v[c4 + 2] + BN_EPS) * (y - m[c4 + 2]) + be[c4 + 2];
    y = fmaxf(dv * h.w + b[c4 + 3], 0.f);
    r.w = g[c4 + 3] * rsqrtf(v[c4 + 3] + BN_EPS) * (y - m[c4 + 3]) + be[c4 + 3];
    out[idx] = r;
}

// ---------------- mean pool by sorted batch ----------------
__device__ __forceinline__ int lower_bound_i(const int* a, int n, int key) {
    int lo = 0, hi = n;
    while (lo < hi) { int mid = (lo + hi) >> 1; if (a[mid] < key) lo = mid + 1; else hi = mid; }
    return lo;
}
__global__ void pool_k(const float* __restrict__ h, const int* __restrict__ batch,
                       float* __restrict__ pooled)
{
    int gph = blockIdx.x;
    __shared__ int s_lo, s_hi;
    if (threadIdx.x == 0) {
        s_lo = lower_bound_i(batch, Nn, gph);
        s_hi = lower_bound_i(batch, Nn, gph + 1);
    }
    __syncthreads();
    int lo = s_lo, hi = s_hi;
    int c = threadIdx.x;                 // DOUT threads
    float acc = 0.f;
    for (int i = lo; i < hi; i++) acc += h[(size_t)i * DOUT + c];
    float cnt = (float)((hi - lo) > 0 ? (hi - lo) : 1);
    pooled[gph * DOUT + c] = acc / cnt;
}

// ---------------- launch ----------------
extern "C" void kernel_launch(void* const* d_in, const int* in_sizes, int n_in,
                              void* d_out, int out_size)
{
    const float* x   = (const float*)d_in[0];
    const int*   ei  = (const int*)  d_in[1];
    const int*   bat = (const int*)  d_in[2];
    const float* W1  = (const float*)d_in[3];
    const float* b1  = (const float*)d_in[4];
    const float* W2  = (const float*)d_in[5];
    const float* b2  = (const float*)d_in[6];
    const float* W3  = (const float*)d_in[7];
    const float* b3  = (const float*)d_in[8];
    const float* g1  = (const float*)d_in[9];
    const float* be1 = (const float*)d_in[10];
    const float* m1  = (const float*)d_in[11];
    const float* v1  = (const float*)d_in[12];
    const float* g2  = (const float*)d_in[13];
    const float* be2 = (const float*)d_in[14];
    const float* m2  = (const float*)d_in[15];
    const float* v2  = (const float*)d_in[16];
    const float* g3  = (const float*)d_in[17];
    const float* be3 = (const float*)d_in[18];
    const float* m3  = (const float*)d_in[19];
    const float* v3  = (const float*)d_in[20];
    const float* Wf1 = (const float*)d_in[21];
    const float* bf1 = (const float*)d_in[22];
    const float* Wf2 = (const float*)d_in[23];
    const float* bf2 = (const float*)d_in[24];

    const int* src = ei;
    const int* dst = ei + Ee;

    float *p_deg, *p_dinv, *p_hs, *p_acc, *p_act, *p_pool, *p_tmp;
    cudaGetSymbolAddress((void**)&p_deg,  g_deg);
    cudaGetSymbolAddress((void**)&p_dinv, g_dinv);
    cudaGetSymbolAddress((void**)&p_hs,   g_hs);
    cudaGetSymbolAddress((void**)&p_acc,  g_acc);
    cudaGetSymbolAddress((void**)&p_act,  g_act);
    cudaGetSymbolAddress((void**)&p_pool, g_pool);
    cudaGetSymbolAddress((void**)&p_tmp,  g_tmp);

    // degree / normalization
    deg_init_k<<<Nn / 256, 256>>>(p_deg);
    deg_acc_k <<<Ee / 256, 256>>>(dst, p_deg);
    dinv_k    <<<Nn / 256, 256>>>(p_deg, p_dinv);

    const int t4_DH   = Nn * DH / 4;
    const int t4_DOUT = Nn * DOUT / 4;
    const int scat_blocks = (Ee * 32) / 256;

    // ---- layer 1: 128 -> 512 ----
    tgemm_k<3><<<dim3(DH / 128, Nn / 128), 256>>>(x, W1, nullptr, p_dinv, p_hs, p_acc, Nn, DIN, DH);
    scatter_k<<<scat_blocks, 256>>>(src, dst, p_hs, p_acc, DH);
    bnrelu_k<<<t4_DH / 256, 256>>>((const float4*)p_acc, p_dinv, b1, g1, be1, m1, v1, (float4*)p_act, DH / 4, t4_DH);

    // ---- layer 2: 512 -> 512 ----
    tgemm_k<3><<<dim3(DH / 128, Nn / 128), 256>>>(p_act, W2, nullptr, p_dinv, p_hs, p_acc, Nn, DH, DH);
    scatter_k<<<scat_blocks, 256>>>(src, dst, p_hs, p_acc, DH);
    bnrelu_k<<<t4_DH / 256, 256>>>((const float4*)p_acc, p_dinv, b2, g2, be2, m2, v2, (float4*)p_act, DH / 4, t4_DH);

    // ---- layer 3: 512 -> 256 ----
    tgemm_k<3><<<dim3(DOUT / 128, Nn / 128), 256>>>(p_act, W3, nullptr, p_dinv, p_hs, p_acc, Nn, DH, DOUT);
    scatter_k<<<scat_blocks, 256>>>(src, dst, p_hs, p_acc, DOUT);
    bnrelu_k<<<t4_DOUT / 256, 256>>>((const float4*)p_acc, p_dinv, b3, g3, be3, m3, v3, (float4*)p_act, DOUT / 4, t4_DOUT);

    // ---- pool + MLP head ----
    pool_k<<<Gg, DOUT>>>(p_act, bat, p_pool);
    tgemm_k<1><<<dim3(DOUT / 128, Gg / 128), 256>>>(p_pool, Wf1, bf1, nullptr, p_tmp, nullptr, Gg, DOUT, DOUT);
    tgemm_k<2><<<dim3(DOUT / 128, Gg / 128), 256>>>(p_tmp, Wf2, bf2, nullptr, (float*)d_out, nullptr, Gg, DOUT, DOUT);
}

// round 3
// speedup vs baseline: 1.6370x; 1.2615x over previous
#include <cuda_runtime.h>
#include <cstddef>

#define Nn   131072
#define Ee   524288
#define Gg   4096
#define DIN  128
#define DH   512
#define DOUT 256
#define BN_EPS 1e-5f

// ---------------- scratch ----------------
__device__ float g_deg [Nn];
__device__ float g_dinv[Nn];
__device__ float g_hs  [(size_t)Nn * DH];
__device__ float g_acc [(size_t)Nn * DH];
__device__ float g_act [(size_t)Nn * DH];
__device__ float g_pool[Gg * DOUT];
__device__ float g_tmp [Gg * DOUT];

// ---------------- degree / norm ----------------
__global__ void deg_init_k(float* deg) {
    int i = blockIdx.x * blockDim.x + threadIdx.x;
    if (i < Nn) deg[i] = 1.0f;
}
__global__ void deg_acc_k(const int* __restrict__ dst, float* deg) {
    int e = blockIdx.x * blockDim.x + threadIdx.x;
    if (e < Ee) atomicAdd(&deg[dst[e]], 1.0f);
}
__global__ void dinv_k(const float* __restrict__ deg, float* dinv) {
    int i = blockIdx.x * blockDim.x + threadIdx.x;
    if (i < Nn) dinv[i] = rsqrtf(deg[i]);
}

// ---------------- tf32 helpers ----------------
__device__ __forceinline__ float to_tf32(float x) {
    unsigned u;
    asm("cvt.rna.tf32.f32 %0, %1;" : "=r"(u) : "f"(x));
    return __uint_as_float(u);
}
__device__ __forceinline__ void mma_tf32(float* d, const float* a, const float* b) {
    asm volatile(
        "mma.sync.aligned.m16n8k8.row.col.f32.tf32.tf32.f32 "
        "{%0,%1,%2,%3}, {%4,%5,%6,%7}, {%8,%9}, {%0,%1,%2,%3};"
        : "+f"(d[0]), "+f"(d[1]), "+f"(d[2]), "+f"(d[3])
        : "r"(__float_as_uint(a[0])), "r"(__float_as_uint(a[1])),
          "r"(__float_as_uint(a[2])), "r"(__float_as_uint(a[3])),
          "r"(__float_as_uint(b[0])), "r"(__float_as_uint(b[1])));
}

// ---------------- tf32 tensor-core GEMM, fragment-major SMEM ----------------
// Block 128x128, BK=32, 8 warps (4M x 2N), warp tile 32x64.
// As_f[ks][mt][g][q^ks]           : float4 = {A[r][kb+q], A[r+8][kb+q], A[r][kb+q+4], A[r+8][kb+q+4]}
// Bs_f[ks][n][q ^ ((n>>2)&3)]     : float2 = {B[kb+q][n], B[kb+q+4][n]}
// EPI: 0 plain | 1 +bias+relu | 2 +bias | 3 GCN (scale dinv[row], dual store)
template <int EPI>
__global__ __launch_bounds__(256, 2) void tgemm_k(
    const float* __restrict__ A, const float* __restrict__ B,
    const float* __restrict__ bias, const float* __restrict__ dinv,
    float* __restrict__ C, float* __restrict__ C2,
    int M, int K, int Nd)
{
    __shared__ float4 As_f[1024];   // 16 KB
    __shared__ float2 Bs_f[2048];   // 16 KB

    const int t    = threadIdx.x;
    const int warp = t >> 5, lane = t & 31;
    const int wm = (warp >> 1) * 32;
    const int wn = (warp & 1) * 64;
    const int grp = lane >> 2, qid = lane & 3;
    const int mt0 = (warp >> 1) * 2, mt1 = mt0 + 1;

    const size_t row0 = (size_t)blockIdx.y * 128;
    const float* Ablk = A + row0 * K;
    const float* Bblk = B + blockIdx.x * 128;

    // A fill mapping: t -> (ks, g, mt)
    const int fa_ks = t & 3, fa_g = (t >> 2) & 7, fa_mt = t >> 5;
    const float* ArowLo = Ablk + (size_t)(fa_mt * 16 + fa_g) * K + fa_ks * 8;
    const float* ArowHi = ArowLo + (size_t)8 * K;
    float4* Abase = &As_f[fa_ks * 256 + fa_mt * 32 + fa_g * 4];

    // B fill mapping: t -> (q, c4, ks)
    const int fb_q = t & 3, fb_c4 = (t >> 2) & 15, fb_ks = t >> 6;
    const float* Brow0 = Bblk + (size_t)(fb_ks * 8 + fb_q) * Nd;
    const float* Brow1 = Brow0 + (size_t)4 * Nd;

    float acc[2][8][4];
    #pragma unroll
    for (int i = 0; i < 2; i++)
        #pragma unroll
        for (int j = 0; j < 8; j++)
            #pragma unroll
            for (int l = 0; l < 4; l++) acc[i][j][l] = 0.f;

    // prefetch A tile (registers)
    float4 pa0, pa1, pb0, pb1;
    pa0 = *(const float4*)(ArowLo);
    pa1 = *(const float4*)(ArowLo + 4);
    pb0 = *(const float4*)(ArowHi);
    pb1 = *(const float4*)(ArowHi + 4);

    for (int k0 = 0; k0 < K; k0 += 32) {
        // ---- store A fragments (STS.128, conflict-free via q^ks swizzle) ----
        {
            const float* qa0 = &pa0.x; const float* qa1 = &pa1.x;
            const float* qb0 = &pb0.x; const float* qb1 = &pb1.x;
            #pragma unroll
            for (int q = 0; q < 4; q++) {
                float4 w;
                w.x = to_tf32(qa0[q]); w.y = to_tf32(qb0[q]);
                w.z = to_tf32(qa1[q]); w.w = to_tf32(qb1[q]);
                Abase[q ^ fa_ks] = w;
            }
        }
        // ---- load + store B fragments ----
        #pragma unroll
        for (int i = 0; i < 2; i++) {
            const int col = fb_c4 * 4 + 64 * i;
            float4 v0 = *(const float4*)(Brow0 + (size_t)k0 * Nd + col);
            float4 v1 = *(const float4*)(Brow1 + (size_t)k0 * Nd + col);
            const float* p0 = &v0.x; const float* p1 = &v1.x;
            #pragma unroll
            for (int jj = 0; jj < 4; jj++) {
                int j = jj ^ fb_q;                  // permuted store order
                int coln = col + j;
                int q2 = fb_q ^ ((coln >> 2) & 3);
                Bs_f[fb_ks * 512 + coln * 4 + q2] = make_float2(to_tf32(p0[j]), to_tf32(p1[j]));
            }
        }
        __syncthreads();

        // prefetch next A tile during compute
        if (k0 + 32 < K) {
            pa0 = *(const float4*)(ArowLo + k0 + 32);
            pa1 = *(const float4*)(ArowLo + k0 + 36);
            pb0 = *(const float4*)(ArowHi + k0 + 32);
            pb1 = *(const float4*)(ArowHi + k0 + 36);
        }

        // ---- compute 4 ksteps ----
        #pragma unroll
        for (int ks = 0; ks < 4; ks++) {
            float4 af0 = As_f[ks * 256 + mt0 * 32 + grp * 4 + (qid ^ ks)];
            float4 af1 = As_f[ks * 256 + mt1 * 32 + grp * 4 + (qid ^ ks)];
            float2 bf[8];
            #pragma unroll
            for (int nt = 0; nt < 8; nt++) {
                int n = wn + nt * 8 + grp;
                bf[nt] = Bs_f[ks * 512 + n * 4 + (qid ^ ((n >> 2) & 3))];
            }
            #pragma unroll
            for (int nt = 0; nt < 8; nt++) {
                mma_tf32(acc[0][nt], &af0.x, &bf[nt].x);
                mma_tf32(acc[1][nt], &af1.x, &bf[nt].x);
            }
        }
        __syncthreads();
    }

    // ---- epilogue ----
    #pragma unroll
    for (int mt = 0; mt < 2; mt++) {
        const int gr0 = (int)row0 + wm + mt * 16 + grp;
        float s0 = 1.f, s1 = 1.f;
        if (EPI == 3) { s0 = dinv[gr0]; s1 = dinv[gr0 + 8]; }
        #pragma unroll
        for (int nt = 0; nt < 8; nt++) {
            int gc = blockIdx.x * 128 + wn + nt * 8 + 2 * qid;
            float2 v0, v1;
            v0.x = acc[mt][nt][0]; v0.y = acc[mt][nt][1];
            v1.x = acc[mt][nt][2]; v1.y = acc[mt][nt][3];
            if (EPI == 3) { v0.x *= s0; v0.y *= s0; v1.x *= s1; v1.y *= s1; }
            if (EPI == 1 || EPI == 2) {
                float bx = bias[gc], by = bias[gc + 1];
                v0.x += bx; v0.y += by; v1.x += bx; v1.y += by;
                if (EPI == 1) {
                    v0.x = fmaxf(v0.x, 0.f); v0.y = fmaxf(v0.y, 0.f);
                    v1.x = fmaxf(v1.x, 0.f); v1.y = fmaxf(v1.y, 0.f);
                }
            }
            *(float2*)(C + (size_t)gr0 * Nd + gc)       = v0;
            *(float2*)(C + (size_t)(gr0 + 8) * Nd + gc) = v1;
            if (EPI == 3) {
                *(float2*)(C2 + (size_t)gr0 * Nd + gc)       = v0;
                *(float2*)(C2 + (size_t)(gr0 + 8) * Nd + gc) = v1;
            }
        }
    }
}

// ---------------- scatter: acc[dst,:] += hs[src,:] ----------------
__device__ __forceinline__ void red_add_v4(float* addr, float4 v) {
    asm volatile("red.global.add.v4.f32 [%0], {%1,%2,%3,%4};"
                 :: "l"(addr), "f"(v.x), "f"(v.y), "f"(v.z), "f"(v.w) : "memory");
}
__global__ void scatter_k(const int* __restrict__ src, const int* __restrict__ dst,
                          const float* __restrict__ hs, float* __restrict__ acc, int Nd)
{
    int w = (blockIdx.x * blockDim.x + threadIdx.x) >> 5;
    int lane = threadIdx.x & 31;
    if (w >= Ee) return;
    int s = src[w], d = dst[w];
    const float4* hp = (const float4*)(hs + (size_t)s * Nd);
    float* ap = acc + (size_t)d * Nd;
    int q = Nd >> 2;
    for (int j = lane; j < q; j += 32)
        red_add_v4(ap + j * 4, hp[j]);
}

// ---------------- act = bn(relu(dinv[node]*acc + b)) ----------------
__global__ void bnrelu_k(const float4* __restrict__ in, const float* __restrict__ dinv,
                         const float* __restrict__ b,
                         const float* __restrict__ g, const float* __restrict__ be,
                         const float* __restrict__ m, const float* __restrict__ v,
                         float4* __restrict__ out, int q, int total4)
{
    int idx = blockIdx.x * blockDim.x + threadIdx.x;
    if (idx >= total4) return;
    int node = idx / q;
    int c4 = (idx - node * q) * 4;
    float dv = dinv[node];
    float4 h = in[idx];
    float4 r;
    float y;
    y = fmaxf(dv * h.x + b[c4 + 0], 0.f);
    r.x = g[c4 + 0] * rsqrtf(v[c4 + 0] + BN_EPS) * (y - m[c4 + 0]) + be[c4 + 0];
    y = fmaxf(dv * h.y + b[c4 + 1], 0.f);
    r.y = g[c4 + 1] * rsqrtf(v[c4 + 1] + BN_EPS) * (y - m[c4 + 1]) + be[c4 + 1];
    y = fmaxf(dv * h.z + b[c4 + 2], 0.f);
    r.z = g[c4 + 2] * rsqrtf(v[c4 + 2] + BN_EPS) * (y - m[c4 + 2]) + be[c4 + 2];
    y = fmaxf(dv * h.w + b[c4 + 3], 0.f);
    r.w = g[c4 + 3] * rsqrtf(v[c4 + 3] + BN_EPS) * (y - m[c4 + 3]) + be[c4 + 3];
    out[idx] = r;
}

// ---------------- mean pool ----------------
__device__ __forceinline__ int lower_bound_i(const int* a, int n, int key) {
    int lo = 0, hi = n;
    while (lo < hi) { int mid = (lo + hi) >> 1; if (a[mid] < key) lo = mid + 1; else hi = mid; }
    return lo;
}
__global__ void pool_k(const float* __restrict__ h, const int* __restrict__ batch,
                       float* __restrict__ pooled)
{
    int gph = blockIdx.x;
    __shared__ int s_lo, s_hi;
    if (threadIdx.x == 0) {
        s_lo = lower_bound_i(batch, Nn, gph);
        s_hi = lower_bound_i(batch, Nn, gph + 1);
    }
    __syncthreads();
    int lo = s_lo, hi = s_hi;
    int c = threadIdx.x;
    float acc = 0.f;
    for (int i = lo; i < hi; i++) acc += h[(size_t)i * DOUT + c];
    float cnt = (float)((hi - lo) > 0 ? (hi - lo) : 1);
    pooled[gph * DOUT + c] = acc / cnt;
}

// ---------------- launch ----------------
extern "C" void kernel_launch(void* const* d_in, const int* in_sizes, int n_in,
                              void* d_out, int out_size)
{
    const float* x   = (const float*)d_in[0];
    const int*   ei  = (const int*)  d_in[1];
    const int*   bat = (const int*)  d_in[2];
    const float* W1  = (const float*)d_in[3];
    const float* b1  = (const float*)d_in[4];
    const float* W2  = (const float*)d_in[5];
    const float* b2  = (const float*)d_in[6];
    const float* W3  = (const float*)d_in[7];
    const float* b3  = (const float*)d_in[8];
    const float* g1  = (const float*)d_in[9];
    const float* be1 = (const float*)d_in[10];
    const float* m1  = (const float*)d_in[11];
    const float* v1  = (const float*)d_in[12];
    const float* g2  = (const float*)d_in[13];
    const float* be2 = (const float*)d_in[14];
    const float* m2  = (const float*)d_in[15];
    const float* v2  = (const float*)d_in[16];
    const float* g3  = (const float*)d_in[17];
    const float* be3 = (const float*)d_in[18];
    const float* m3  = (const float*)d_in[19];
    const float* v3  = (const float*)d_in[20];
    const float* Wf1 = (const float*)d_in[21];
    const float* bf1 = (const float*)d_in[22];
    const float* Wf2 = (const float*)d_in[23];
    const float* bf2 = (const float*)d_in[24];

    const int* src = ei;
    const int* dst = ei + Ee;

    float *p_deg, *p_dinv, *p_hs, *p_acc, *p_act, *p_pool, *p_tmp;
    cudaGetSymbolAddress((void**)&p_deg,  g_deg);
    cudaGetSymbolAddress((void**)&p_dinv, g_dinv);
    cudaGetSymbolAddress((void**)&p_hs,   g_hs);
    cudaGetSymbolAddress((void**)&p_acc,  g_acc);
    cudaGetSymbolAddress((void**)&p_act,  g_act);
    cudaGetSymbolAddress((void**)&p_pool, g_pool);
    cudaGetSymbolAddress((void**)&p_tmp,  g_tmp);

    deg_init_k<<<Nn / 256, 256>>>(p_deg);
    deg_acc_k <<<Ee / 256, 256>>>(dst, p_deg);
    dinv_k    <<<Nn / 256, 256>>>(p_deg, p_dinv);

    const int t4_DH   = Nn * DH / 4;
    const int t4_DOUT = Nn * DOUT / 4;
    const int scat_blocks = (Ee * 32) / 256;

    // ---- layer 1 ----
    tgemm_k<3><<<dim3(DH / 128, Nn / 128), 256>>>(x, W1, nullptr, p_dinv, p_hs, p_acc, Nn, DIN, DH);
    scatter_k<<<scat_blocks, 256>>>(src, dst, p_hs, p_acc, DH);
    bnrelu_k<<<t4_DH / 256, 256>>>((const float4*)p_acc, p_dinv, b1, g1, be1, m1, v1, (float4*)p_act, DH / 4, t4_DH);

    // ---- layer 2 ----
    tgemm_k<3><<<dim3(DH / 128, Nn / 128), 256>>>(p_act, W2, nullptr, p_dinv, p_hs, p_acc, Nn, DH, DH);
    scatter_k<<<scat_blocks, 256>>>(src, dst, p_hs, p_acc, DH);
    bnrelu_k<<<t4_DH / 256, 256>>>((const float4*)p_acc, p_dinv, b2, g2, be2, m2, v2, (float4*)p_act, DH / 4, t4_DH);

    // ---- layer 3 ----
    tgemm_k<3><<<dim3(DOUT / 128, Nn / 128), 256>>>(p_act, W3, nullptr, p_dinv, p_hs, p_acc, Nn, DH, DOUT);
    scatter_k<<<scat_blocks, 256>>>(src, dst, p_hs, p_acc, DOUT);
    bnrelu_k<<<t4_DOUT / 256, 256>>>((const float4*)p_acc, p_dinv, b3, g3, be3, m3, v3, (float4*)p_act, DOUT / 4, t4_DOUT);

    // ---- pool + MLP head ----
    pool_k<<<Gg, DOUT>>>(p_act, bat, p_pool);
    tgemm_k<1><<<dim3(DOUT / 128, Gg / 128), 256>>>(p_pool, Wf1, bf1, nullptr, p_tmp, nullptr, Gg, DOUT, DOUT);
    tgemm_k<2><<<dim3(DOUT / 128, Gg / 128), 256>>>(p_tmp, Wf2, bf2, nullptr, (float*)d_out, nullptr, Gg, DOUT, DOUT);
}

// round 4
// speedup vs baseline: 1.8503x; 1.1303x over previous
#include <cuda_runtime.h>
#include <cstddef>

#define Nn   131072
#define Ee   524288
#define Gg   4096
#define DIN  128
#define DH   512
#define DOUT 256
#define BN_EPS 1e-5f

// ---------------- scratch ----------------
__device__ float g_deg [Nn];
__device__ float g_dinv[Nn];
__device__ float g_hs  [(size_t)Nn * DH];
__device__ float g_acc [(size_t)Nn * DH];
__device__ float g_act [(size_t)Nn * DH];
__device__ float g_pool[Gg * DOUT];
__device__ float g_tmp [Gg * DOUT];
__device__ float4 g_bpack[65536];           // packed B fragments (max 512x512)

// ---------------- degree / norm ----------------
__global__ void deg_init_k(float* deg) {
    int i = blockIdx.x * blockDim.x + threadIdx.x;
    if (i < Nn) deg[i] = 1.0f;
}
__global__ void deg_acc_k(const int* __restrict__ dst, float* deg) {
    int e = blockIdx.x * blockDim.x + threadIdx.x;
    if (e < Ee) atomicAdd(&deg[dst[e]], 1.0f);
}
__global__ void dinv_k(const float* __restrict__ deg, float* dinv) {
    int i = blockIdx.x * blockDim.x + threadIdx.x;
    if (i < Nn) dinv[i] = rsqrtf(deg[i]);
}

// ---------------- tf32 helpers ----------------
__device__ __forceinline__ float to_tf32(float x) {
    unsigned u;
    asm("cvt.rna.tf32.f32 %0, %1;" : "=r"(u) : "f"(x));
    return __uint_as_float(u);
}
__device__ __forceinline__ void mma_tf32(float* d, const float* a, const float* b) {
    asm volatile(
        "mma.sync.aligned.m16n8k8.row.col.f32.tf32.tf32.f32 "
        "{%0,%1,%2,%3}, {%4,%5,%6,%7}, {%8,%9}, {%0,%1,%2,%3};"
        : "+f"(d[0]), "+f"(d[1]), "+f"(d[2]), "+f"(d[3])
        : "r"(__float_as_uint(a[0])), "r"(__float_as_uint(a[1])),
          "r"(__float_as_uint(a[2])), "r"(__float_as_uint(a[3])),
          "r"(__float_as_uint(b[0])), "r"(__float_as_uint(b[1])));
}
__device__ __forceinline__ void cp_async16(void* smem, const void* gmem) {
    unsigned s = (unsigned)__cvta_generic_to_shared(smem);
    asm volatile("cp.async.cg.shared.global [%0], [%1], 16;" :: "r"(s), "l"(gmem));
}

// ---------------- cvt copy: x -> act (tf32-rounded) ----------------
__global__ void cvt_copy_k(const float4* __restrict__ in, float4* __restrict__ out, int n4) {
    int i = blockIdx.x * blockDim.x + threadIdx.x;
    if (i >= n4) return;
    float4 v = in[i];
    v.x = to_tf32(v.x); v.y = to_tf32(v.y); v.z = to_tf32(v.z); v.w = to_tf32(v.w);
    out[i] = v;
}

// ---------------- pack B: W[K,Nd] row-major -> fragment-major tf32 ----------------
// out[((k0/32)*nb + bxn)*1024 + ks*256 + ntpl*32 + grp*4 + q] =
//   { W[kr][n0], W[kr+4][n0], W[kr][n1], W[kr+4][n1] },  kr = k0+ks*8+q,
//   n0 = bxn*128 + ntpl*16 + grp, n1 = n0+8, nb = Nd/128
__global__ void packB_k(const float* __restrict__ W, float4* __restrict__ out, int K, int Nd) {
    int idx = blockIdx.x * blockDim.x + threadIdx.x;
    int total = (K >> 5) * (Nd >> 7) * 1024;
    if (idx >= total) return;
    int q = idx & 3, grp = (idx >> 2) & 7, ntpl = (idx >> 5) & 7, ks = (idx >> 8) & 3;
    int tile = idx >> 10;
    int nb = Nd >> 7;
    int k0 = (tile / nb) * 32, bxn = tile % nb;
    int n0 = bxn * 128 + ntpl * 16 + grp;
    int kr = k0 + ks * 8 + q;
    float4 v;
    v.x = to_tf32(W[(size_t)kr * Nd + n0]);
    v.y = to_tf32(W[(size_t)(kr + 4) * Nd + n0]);
    v.z = to_tf32(W[(size_t)kr * Nd + n0 + 8]);
    v.w = to_tf32(W[(size_t)(kr + 4) * Nd + n0 + 8]);
    out[idx] = v;
}

// ---------------- tf32 tensor GEMM, prepacked B, double-buffered ----------------
// Block 128x128, BK=32, 8 warps (4M x 2N), warp tile 32x64.
// A assumed tf32-rounded already. EPI: 1 +bias+relu(+cvt) | 2 +bias | 3 GCN
template <int EPI>
__global__ __launch_bounds__(256, 2) void tgemm_k(
    const float* __restrict__ A, const float4* __restrict__ Bp,
    const float* __restrict__ bias, const float* __restrict__ dinv,
    float* __restrict__ C, float* __restrict__ C2,
    int M, int K, int Nd)
{
    extern __shared__ float4 smem4[];
    float4* As = smem4;          // [2][1024]
    float4* Bs = smem4 + 2048;   // [2][1024]

    const int t    = threadIdx.x;
    const int warp = t >> 5, lane = t & 31;
    const int wm = (warp >> 1) * 32;
    const int wn = (warp & 1) * 64;
    const int grp = lane >> 2, qid = lane & 3;
    const int mt0 = (warp >> 1) * 2, mt1 = mt0 + 1;
    const int nb = Nd >> 7;
    const int T = K >> 5;

    const size_t row0 = (size_t)blockIdx.y * 128;
    const float* Ablk = A + row0 * K;

    // A fill mapping
    const int fa_ks = t & 3, fa_g = (t >> 2) & 7, fa_mt = t >> 5;
    const float* ArowLo = Ablk + (size_t)(fa_mt * 16 + fa_g) * K + fa_ks * 8;
    const float* ArowHi = ArowLo + (size_t)8 * K;
    const int fa_idx = fa_ks * 256 + fa_mt * 32 + fa_g * 4;

    float acc[2][8][4];
    #pragma unroll
    for (int i = 0; i < 2; i++)
        #pragma unroll
        for (int j = 0; j < 8; j++)
            #pragma unroll
            for (int l = 0; l < 4; l++) acc[i][j][l] = 0.f;

    float4 ra0, ra1, rb0, rb1;
    ra0 = *(const float4*)(ArowLo);
    ra1 = *(const float4*)(ArowLo + 4);
    rb0 = *(const float4*)(ArowHi);
    rb1 = *(const float4*)(ArowHi + 4);

    // prologue: B stage0 via cp.async, A stage0 via STS
    {
        const float4* bsrc = Bp + ((size_t)blockIdx.x) * 1024 + t * 4;
        #pragma unroll
        for (int j = 0; j < 4; j++) cp_async16(&Bs[t * 4 + j], bsrc + j);
        asm volatile("cp.async.commit_group;");
        const float* qa0 = &ra0.x; const float* qa1 = &ra1.x;
        const float* qb0 = &rb0.x; const float* qb1 = &rb1.x;
        #pragma unroll
        for (int q = 0; q < 4; q++)
            As[fa_idx + (q ^ fa_ks)] = make_float4(qa0[q], qb0[q], qa1[q], qb1[q]);
        asm volatile("cp.async.wait_group 0;");
    }
    __syncthreads();

    for (int i = 0; i < T; i++) {
        const int st = i & 1;
        const bool more = (i + 1 < T);
        if (more) {
            const int kn = (i + 1) * 32;
            ra0 = *(const float4*)(ArowLo + kn);
            ra1 = *(const float4*)(ArowLo + kn + 4);
            rb0 = *(const float4*)(ArowHi + kn);
            rb1 = *(const float4*)(ArowHi + kn + 4);
            const float4* bsrc = Bp + ((size_t)(i + 1) * nb + blockIdx.x) * 1024 + t * 4;
            float4* bdst = &Bs[(1 - st) * 1024 + t * 4];
            #pragma unroll
            for (int j = 0; j < 4; j++) cp_async16(bdst + j, bsrc + j);
            asm volatile("cp.async.commit_group;");
        }

        // compute 4 ksteps from stage st
        const float4* Ast = &As[st * 1024];
        const float4* Bst = &Bs[st * 1024];
        #pragma unroll
        for (int ks = 0; ks < 4; ks++) {
            float4 af0 = Ast[ks * 256 + mt0 * 32 + grp * 4 + (qid ^ ks)];
            float4 af1 = Ast[ks * 256 + mt1 * 32 + grp * 4 + (qid ^ ks)];
            float4 bfp[4];
            #pragma unroll
            for (int p = 0; p < 4; p++) {
                int ntpl = (wn >> 4) + p;
                bfp[p] = Bst[ks * 256 + ntpl * 32 + grp * 4 + qid];
            }
            #pragma unroll
            for (int p = 0; p < 4; p++) {
                mma_tf32(acc[0][2 * p],     &af0.x, &bfp[p].x);
                mma_tf32(acc[0][2 * p + 1], &af0.x, &bfp[p].z);
                mma_tf32(acc[1][2 * p],     &af1.x, &bfp[p].x);
                mma_tf32(acc[1][2 * p + 1], &af1.x, &bfp[p].z);
            }
        }

        if (more) {
            float4* Adst = &As[(1 - st) * 1024];
            const float* qa0 = &ra0.x; const float* qa1 = &ra1.x;
            const float* qb0 = &rb0.x; const float* qb1 = &rb1.x;
            #pragma unroll
            for (int q = 0; q < 4; q++)
                Adst[fa_idx + (q ^ fa_ks)] = make_float4(qa0[q], qb0[q], qa1[q], qb1[q]);
            asm volatile("cp.async.wait_group 0;");
        }
        __syncthreads();
    }

    // ---- epilogue ----
    #pragma unroll
    for (int mt = 0; mt < 2; mt++) {
        const int gr0 = (int)row0 + wm + mt * 16 + grp;
        float s0 = 1.f, s1 = 1.f;
        if (EPI == 3) { s0 = dinv[gr0]; s1 = dinv[gr0 + 8]; }
        #pragma unroll
        for (int nt = 0; nt < 8; nt++) {
            int gc = blockIdx.x * 128 + wn + nt * 8 + 2 * qid;
            float2 v0, v1;
            v0.x = acc[mt][nt][0]; v0.y = acc[mt][nt][1];
            v1.x = acc[mt][nt][2]; v1.y = acc[mt][nt][3];
            if (EPI == 3) { v0.x *= s0; v0.y *= s0; v1.x *= s1; v1.y *= s1; }
            if (EPI == 1 || EPI == 2) {
                float bx = bias[gc], by = bias[gc + 1];
                v0.x += bx; v0.y += by; v1.x += bx; v1.y += by;
                if (EPI == 1) {
                    v0.x = to_tf32(fmaxf(v0.x, 0.f)); v0.y = to_tf32(fmaxf(v0.y, 0.f));
                    v1.x = to_tf32(fmaxf(v1.x, 0.f)); v1.y = to_tf32(fmaxf(v1.y, 0.f));
                }
            }
            *(float2*)(C + (size_t)gr0 * Nd + gc)       = v0;
            *(float2*)(C + (size_t)(gr0 + 8) * Nd + gc) = v1;
            if (EPI == 3) {
                *(float2*)(C2 + (size_t)gr0 * Nd + gc)       = v0;
                *(float2*)(C2 + (size_t)(gr0 + 8) * Nd + gc) = v1;
            }
        }
    }
}

// ---------------- scatter: acc[dst,:] += hs[src,:] ----------------
__device__ __forceinline__ void red_add_v4(float* addr, float4 v) {
    asm volatile("red.global.add.v4.f32 [%0], {%1,%2,%3,%4};"
                 :: "l"(addr), "f"(v.x), "f"(v.y), "f"(v.z), "f"(v.w) : "memory");
}
__global__ void scatter_k(const int* __restrict__ src, const int* __restrict__ dst,
                          const float* __restrict__ hs, float* __restrict__ acc, int Nd)
{
    int w = (blockIdx.x * blockDim.x + threadIdx.x) >> 5;
    int lane = threadIdx.x & 31;
    if (w >= Ee) return;
    int s = src[w], d = dst[w];
    const float4* hp = (const float4*)(hs + (size_t)s * Nd);
    float* ap = acc + (size_t)d * Nd;
    int q = Nd >> 2;
    for (int j = lane; j < q; j += 32)
        red_add_v4(ap + j * 4, hp[j]);
}

// ---------------- act = bn(relu(dinv*acc + b)); CVT: tf32-round output ----------------
template <bool CVT>
__global__ void bnrelu_k(const float4* __restrict__ in, const float* __restrict__ dinv,
                         const float* __restrict__ b,
                         const float* __restrict__ g, const float* __restrict__ be,
                         const float* __restrict__ m, const float* __restrict__ v,
                         float4* __restrict__ out, int q, int total4)
{
    int idx = blockIdx.x * blockDim.x + threadIdx.x;
    if (idx >= total4) return;
    int node = idx / q;
    int c4 = (idx - node * q) * 4;
    float dv = dinv[node];
    float4 h = in[idx];
    float4 r;
    float y;
    y = fmaxf(dv * h.x + b[c4 + 0], 0.f);
    r.x = g[c4 + 0] * rsqrtf(v[c4 + 0] + BN_EPS) * (y - m[c4 + 0]) + be[c4 + 0];
    y = fmaxf(dv * h.y + b[c4 + 1], 0.f);
    r.y = g[c4 + 1] * rsqrtf(v[c4 + 1] + BN_EPS) * (y - m[c4 + 1]) + be[c4 + 1];
    y = fmaxf(dv * h.z + b[c4 + 2], 0.f);
    r.z = g[c4 + 2] * rsqrtf(v[c4 + 2] + BN_EPS) * (y - m[c4 + 2]) + be[c4 + 2];
    y = fmaxf(dv * h.w + b[c4 + 3], 0.f);
    r.w = g[c4 + 3] * rsqrtf(v[c4 + 3] + BN_EPS) * (y - m[c4 + 3]) + be[c4 + 3];
    if (CVT) {
        r.x = to_tf32(r.x); r.y = to_tf32(r.y); r.z = to_tf32(r.z); r.w = to_tf32(r.w);
    }
    out[idx] = r;
}

// ---------------- mean pool (tf32-rounded output for MLP GEMM) ----------------
__device__ __forceinline__ int lower_bound_i(const int* a, int n, int key) {
    int lo = 0, hi = n;
    while (lo < hi) { int mid = (lo + hi) >> 1; if (a[mid] < key) lo = mid + 1; else hi = mid; }
    return lo;
}
__global__ void pool_k(const float* __restrict__ h, const int* __restrict__ batch,
                       float* __restrict__ pooled)
{
    int gph = blockIdx.x;
    __shared__ int s_lo, s_hi;
    if (threadIdx.x == 0) {
        s_lo = lower_bound_i(batch, Nn, gph);
        s_hi = lower_bound_i(batch, Nn, gph + 1);
    }
    __syncthreads();
    int lo = s_lo, hi = s_hi;
    int c = threadIdx.x;
    float acc = 0.f;
    for (int i = lo; i < hi; i++) acc += h[(size_t)i * DOUT + c];
    float cnt = (float)((hi - lo) > 0 ? (hi - lo) : 1);
    pooled[gph * DOUT + c] = to_tf32(acc / cnt);
}

// ---------------- launch ----------------
extern "C" void kernel_launch(void* const* d_in, const int* in_sizes, int n_in,
                              void* d_out, int out_size)
{
    const float* x   = (const float*)d_in[0];
    const int*   ei  = (const int*)  d_in[1];
    const int*   bat = (const int*)  d_in[2];
    const float* W1  = (const float*)d_in[3];
    const float* b1  = (const float*)d_in[4];
    const float* W2  = (const float*)d_in[5];
    const float* b2  = (const float*)d_in[6];
    const float* W3  = (const float*)d_in[7];
    const float* b3  = (const float*)d_in[8];
    const float* g1  = (const float*)d_in[9];
    const float* be1 = (const float*)d_in[10];
    const float* m1  = (const float*)d_in[11];
    const float* v1  = (const float*)d_in[12];
    const float* g2  = (const float*)d_in[13];
    const float* be2 = (const float*)d_in[14];
    const float* m2  = (const float*)d_in[15];
    const float* v2  = (const float*)d_in[16];
    const float* g3  = (const float*)d_in[17];
    const float* be3 = (const float*)d_in[18];
    const float* m3  = (const float*)d_in[19];
    const float* v3  = (const float*)d_in[20];
    const float* Wf1 = (const float*)d_in[21];
    const float* bf1 = (const float*)d_in[22];
    const float* Wf2 = (const float*)d_in[23];
    const float* bf2 = (const float*)d_in[24];

    const int* src = ei;
    const int* dst = ei + Ee;

    float *p_deg, *p_dinv, *p_hs, *p_acc, *p_act, *p_pool, *p_tmp;
    float4* p_bp;
    cudaGetSymbolAddress((void**)&p_deg,  g_deg);
    cudaGetSymbolAddress((void**)&p_dinv, g_dinv);
    cudaGetSymbolAddress((void**)&p_hs,   g_hs);
    cudaGetSymbolAddress((void**)&p_acc,  g_acc);
    cudaGetSymbolAddress((void**)&p_act,  g_act);
    cudaGetSymbolAddress((void**)&p_pool, g_pool);
    cudaGetSymbolAddress((void**)&p_tmp,  g_tmp);
    cudaGetSymbolAddress((void**)&p_bp,   g_bpack);

    const int SMEM = 65536;
    cudaFuncSetAttribute(tgemm_k<3>, cudaFuncAttributeMaxDynamicSharedMemorySize, SMEM);
    cudaFuncSetAttribute(tgemm_k<1>, cudaFuncAttributeMaxDynamicSharedMemorySize, SMEM);
    cudaFuncSetAttribute(tgemm_k<2>, cudaFuncAttributeMaxDynamicSharedMemorySize, SMEM);

    deg_init_k<<<Nn / 256, 256>>>(p_deg);
    deg_acc_k <<<Ee / 256, 256>>>(dst, p_deg);
    dinv_k    <<<Nn / 256, 256>>>(p_deg, p_dinv);

    const int t4_DH   = Nn * DH / 4;
    const int t4_DOUT = Nn * DOUT / 4;
    const int scat_blocks = (Ee * 32) / 256;

    // layer-1 A: tf32-rounded copy of x into g_act
    cvt_copy_k<<<(Nn * DIN / 4) / 256, 256>>>((const float4*)x, (float4*)p_act, Nn * DIN / 4);

    // ---- layer 1 ----
    packB_k<<<(DIN/32)*(DH/128)*1024/256, 256>>>(W1, p_bp, DIN, DH);
    tgemm_k<3><<<dim3(DH/128, Nn/128), 256, SMEM>>>(p_act, p_bp, nullptr, p_dinv, p_hs, p_acc, Nn, DIN, DH);
    scatter_k<<<scat_blocks, 256>>>(src, dst, p_hs, p_acc, DH);
    bnrelu_k<true><<<t4_DH/256, 256>>>((const float4*)p_acc, p_dinv, b1, g1, be1, m1, v1, (float4*)p_act, DH/4, t4_DH);

    // ---- layer 2 ----
    packB_k<<<(DH/32)*(DH/128)*1024/256, 256>>>(W2, p_bp, DH, DH);
    tgemm_k<3><<<dim3(DH/128, Nn/128), 256, SMEM>>>(p_act, p_bp, nullptr, p_dinv, p_hs, p_acc, Nn, DH, DH);
    scatter_k<<<scat_blocks, 256>>>(src, dst, p_hs, p_acc, DH);
    bnrelu_k<true><<<t4_DH/256, 256>>>((const float4*)p_acc, p_dinv, b2, g2, be2, m2, v2, (float4*)p_act, DH/4, t4_DH);

    // ---- layer 3 ----
    packB_k<<<(DH/32)*(DOUT/128)*1024/256, 256>>>(W3, p_bp, DH, DOUT);
    tgemm_k<3><<<dim3(DOUT/128, Nn/128), 256, SMEM>>>(p_act, p_bp, nullptr, p_dinv, p_hs, p_acc, Nn, DH, DOUT);
    scatter_k<<<scat_blocks, 256>>>(src, dst, p_hs, p_acc, DOUT);
    bnrelu_k<false><<<t4_DOUT/256, 256>>>((const float4*)p_acc, p_dinv, b3, g3, be3, m3, v3, (float4*)p_act, DOUT/4, t4_DOUT);

    // ---- pool + MLP head ----
    pool_k<<<Gg, DOUT>>>(p_act, bat, p_pool);
    packB_k<<<(DOUT/32)*(DOUT/128)*1024/256, 256>>>(Wf1, p_bp, DOUT, DOUT);
    tgemm_k<1><<<dim3(DOUT/128, Gg/128), 256, SMEM>>>(p_pool, p_bp, bf1, nullptr, p_tmp, nullptr, Gg, DOUT, DOUT);
    packB_k<<<(DOUT/32)*(DOUT/128)*1024/256, 256>>>(Wf2, p_bp, DOUT, DOUT);
    tgemm_k<2><<<dim3(DOUT/128, Gg/128), 256, SMEM>>>(p_tmp, p_bp, bf2, nullptr, (float*)d_out, nullptr, Gg, DOUT, DOUT);
}

// round 5
// speedup vs baseline: 3.0272x; 1.6361x over previous
#include <cuda_runtime.h>
#include <cstddef>

#define Nn   131072
#define Ee   524288
#define Gg   4096
#define DIN  128
#define DH   512
#define DOUT 256
#define BN_EPS 1e-5f

// ---------------- scratch ----------------
__device__ float g_deg [Nn];
__device__ float g_dinv[Nn];
__device__ float g_hs  [(size_t)Nn * DH];
__device__ float g_act [(size_t)Nn * DH];
__device__ float g_pool[Gg * DOUT];
__device__ float g_tmp [Gg * DOUT];
__device__ float4 g_bpack[65536];
__device__ int   g_edeg [Nn];
__device__ int   g_offs [Nn + 1];
__device__ int   g_cur  [Nn];
__device__ int   g_eidx [Ee];
__device__ int   g_part [256];

// ---------------- degree / norm ----------------
__global__ void deg_init_k(float* deg, int* edeg) {
    int i = blockIdx.x * blockDim.x + threadIdx.x;
    if (i < Nn) { deg[i] = 1.0f; edeg[i] = 0; }
}
__global__ void deg_acc_k(const int* __restrict__ dst, float* deg, int* edeg) {
    int e = blockIdx.x * blockDim.x + threadIdx.x;
    if (e < Ee) { int d = dst[e]; atomicAdd(&deg[d], 1.0f); atomicAdd(&edeg[d], 1); }
}
__global__ void dinv_k(const float* __restrict__ deg, float* dinv) {
    int i = blockIdx.x * blockDim.x + threadIdx.x;
    if (i < Nn) dinv[i] = rsqrtf(deg[i]);
}

// ---------------- CSR build: exclusive scan of edeg ----------------
__global__ void scan1_k(const int* __restrict__ in, int* out, int* part) {
    __shared__ int s[512];
    int b = blockIdx.x, t = threadIdx.x;
    int v = in[b * 512 + t];
    s[t] = v; __syncthreads();
    #pragma unroll
    for (int o = 1; o < 512; o <<= 1) {
        int x = (t >= o) ? s[t - o] : 0;
        __syncthreads();
        s[t] += x;
        __syncthreads();
    }
    out[b * 512 + t] = s[t] - v;
    if (t == 511) part[b] = s[t];
}
__global__ void scan2_k(int* part) {
    __shared__ int s[256];
    int t = threadIdx.x;
    int v = part[t];
    s[t] = v; __syncthreads();
    #pragma unroll
    for (int o = 1; o < 256; o <<= 1) {
        int x = (t >= o) ? s[t - o] : 0;
        __syncthreads();
        s[t] += x;
        __syncthreads();
    }
    part[t] = s[t] - v;
}
__global__ void scan3_k(int* offs, int* cur, const int* __restrict__ part) {
    int i = blockIdx.x * blockDim.x + threadIdx.x;
    if (i < Nn) {
        int o = offs[i] + part[i >> 9];
        offs[i] = o;
        cur[i] = o;
    }
    if (i == 0) offs[Nn] = Ee;
}
__global__ void fill_k(const int* __restrict__ src, const int* __restrict__ dst,
                       int* cur, int* eidx) {
    int e = blockIdx.x * blockDim.x + threadIdx.x;
    if (e >= Ee) return;
    int d = dst[e];
    int pos = atomicAdd(&cur[d], 1);
    eidx[pos] = src[e];
}

// ---------------- tf32 helpers ----------------
__device__ __forceinline__ float to_tf32(float x) {
    unsigned u;
    asm("cvt.rna.tf32.f32 %0, %1;" : "=r"(u) : "f"(x));
    return __uint_as_float(u);
}
__device__ __forceinline__ void mma_tf32(float* d, const float* a, const float* b) {
    asm volatile(
        "mma.sync.aligned.m16n8k8.row.col.f32.tf32.tf32.f32 "
        "{%0,%1,%2,%3}, {%4,%5,%6,%7}, {%8,%9}, {%0,%1,%2,%3};"
        : "+f"(d[0]), "+f"(d[1]), "+f"(d[2]), "+f"(d[3])
        : "r"(__float_as_uint(a[0])), "r"(__float_as_uint(a[1])),
          "r"(__float_as_uint(a[2])), "r"(__float_as_uint(a[3])),
          "r"(__float_as_uint(b[0])), "r"(__float_as_uint(b[1])));
}
__device__ __forceinline__ void cp_async16(void* smem, const void* gmem) {
    unsigned s = (unsigned)__cvta_generic_to_shared(smem);
    asm volatile("cp.async.cg.shared.global [%0], [%1], 16;" :: "r"(s), "l"(gmem));
}

// ---------------- cvt copy: x -> act (tf32-rounded) ----------------
__global__ void cvt_copy_k(const float4* __restrict__ in, float4* __restrict__ out, int n4) {
    int i = blockIdx.x * blockDim.x + threadIdx.x;
    if (i >= n4) return;
    float4 v = in[i];
    v.x = to_tf32(v.x); v.y = to_tf32(v.y); v.z = to_tf32(v.z); v.w = to_tf32(v.w);
    out[i] = v;
}

// ---------------- pack B ----------------
__global__ void packB_k(const float* __restrict__ W, float4* __restrict__ out, int K, int Nd) {
    int idx = blockIdx.x * blockDim.x + threadIdx.x;
    int total = (K >> 5) * (Nd >> 7) * 1024;
    if (idx >= total) return;
    int q = idx & 3, grp = (idx >> 2) & 7, ntpl = (idx >> 5) & 7, ks = (idx >> 8) & 3;
    int tile = idx >> 10;
    int nb = Nd >> 7;
    int k0 = (tile / nb) * 32, bxn = tile % nb;
    int n0 = bxn * 128 + ntpl * 16 + grp;
    int kr = k0 + ks * 8 + q;
    float4 v;
    v.x = to_tf32(W[(size_t)kr * Nd + n0]);
    v.y = to_tf32(W[(size_t)(kr + 4) * Nd + n0]);
    v.z = to_tf32(W[(size_t)kr * Nd + n0 + 8]);
    v.w = to_tf32(W[(size_t)(kr + 4) * Nd + n0 + 8]);
    out[idx] = v;
}

// ---------------- tf32 tensor GEMM, prepacked B, double-buffered ----------------
// EPI: 1 +bias+relu(+cvt) | 2 +bias | 3 scale-by-dinv[row]
template <int EPI>
__global__ __launch_bounds__(256, 2) void tgemm_k(
    const float* __restrict__ A, const float4* __restrict__ Bp,
    const float* __restrict__ bias, const float* __restrict__ dinv,
    float* __restrict__ C,
    int M, int K, int Nd)
{
    extern __shared__ float4 smem4[];
    float4* As = smem4;          // [2][1024]
    float4* Bs = smem4 + 2048;   // [2][1024]

    const int t    = threadIdx.x;
    const int warp = t >> 5, lane = t & 31;
    const int wm = (warp >> 1) * 32;
    const int wn = (warp & 1) * 64;
    const int grp = lane >> 2, qid = lane & 3;
    const int mt0 = (warp >> 1) * 2, mt1 = mt0 + 1;
    const int nb = Nd >> 7;
    const int T = K >> 5;

    const size_t row0 = (size_t)blockIdx.y * 128;
    const float* Ablk = A + row0 * K;

    const int fa_ks = t & 3, fa_g = (t >> 2) & 7, fa_mt = t >> 5;
    const float* ArowLo = Ablk + (size_t)(fa_mt * 16 + fa_g) * K + fa_ks * 8;
    const float* ArowHi = ArowLo + (size_t)8 * K;
    const int fa_idx = fa_ks * 256 + fa_mt * 32 + fa_g * 4;

    float acc[2][8][4];
    #pragma unroll
    for (int i = 0; i < 2; i++)
        #pragma unroll
        for (int j = 0; j < 8; j++)
            #pragma unroll
            for (int l = 0; l < 4; l++) acc[i][j][l] = 0.f;

    float4 ra0, ra1, rb0, rb1;
    ra0 = *(const float4*)(ArowLo);
    ra1 = *(const float4*)(ArowLo + 4);
    rb0 = *(const float4*)(ArowHi);
    rb1 = *(const float4*)(ArowHi + 4);

    {
        const float4* bsrc = Bp + ((size_t)blockIdx.x) * 1024 + t * 4;
        #pragma unroll
        for (int j = 0; j < 4; j++) cp_async16(&Bs[t * 4 + j], bsrc + j);
        asm volatile("cp.async.commit_group;");
        const float* qa0 = &ra0.x; const float* qa1 = &ra1.x;
        const float* qb0 = &rb0.x; const float* qb1 = &rb1.x;
        #pragma unroll
        for (int q = 0; q < 4; q++)
            As[fa_idx + (q ^ fa_ks)] = make_float4(qa0[q], qb0[q], qa1[q], qb1[q]);
        asm volatile("cp.async.wait_group 0;");
    }
    __syncthreads();

    for (int i = 0; i < T; i++) {
        const int st = i & 1;
        const bool more = (i + 1 < T);
        if (more) {
            const int kn = (i + 1) * 32;
            ra0 = *(const float4*)(ArowLo + kn);
            ra1 = *(const float4*)(ArowLo + kn + 4);
            rb0 = *(const float4*)(ArowHi + kn);
            rb1 = *(const float4*)(ArowHi + kn + 4);
            const float4* bsrc = Bp + ((size_t)(i + 1) * nb + blockIdx.x) * 1024 + t * 4;
            float4* bdst = &Bs[(1 - st) * 1024 + t * 4];
            #pragma unroll
            for (int j = 0; j < 4; j++) cp_async16(bdst + j, bsrc + j);
            asm volatile("cp.async.commit_group;");
        }

        const float4* Ast = &As[st * 1024];
        const float4* Bst = &Bs[st * 1024];
        #pragma unroll
        for (int ks = 0; ks < 4; ks++) {
            float4 af0 = Ast[ks * 256 + mt0 * 32 + grp * 4 + (qid ^ ks)];
            float4 af1 = Ast[ks * 256 + mt1 * 32 + grp * 4 + (qid ^ ks)];
            float4 bfp[4];
            #pragma unroll
            for (int p = 0; p < 4; p++) {
                int ntpl = (wn >> 4) + p;
                bfp[p] = Bst[ks * 256 + ntpl * 32 + grp * 4 + qid];
            }
            #pragma unroll
            for (int p = 0; p < 4; p++) {
                mma_tf32(acc[0][2 * p],     &af0.x, &bfp[p].x);
                mma_tf32(acc[0][2 * p + 1], &af0.x, &bfp[p].z);
                mma_tf32(acc[1][2 * p],     &af1.x, &bfp[p].x);
                mma_tf32(acc[1][2 * p + 1], &af1.x, &bfp[p].z);
            }
        }

        if (more) {
            float4* Adst = &As[(1 - st) * 1024];
            const float* qa0 = &ra0.x; const float* qa1 = &ra1.x;
            const float* qb0 = &rb0.x; const float* qb1 = &rb1.x;
            #pragma unroll
            for (int q = 0; q < 4; q++)
                Adst[fa_idx + (q ^ fa_ks)] = make_float4(qa0[q], qb0[q], qa1[q], qb1[q]);
            asm volatile("cp.async.wait_group 0;");
        }
        __syncthreads();
    }

    #pragma unroll
    for (int mt = 0; mt < 2; mt++) {
        const int gr0 = (int)row0 + wm + mt * 16 + grp;
        float s0 = 1.f, s1 = 1.f;
        if (EPI == 3) { s0 = dinv[gr0]; s1 = dinv[gr0 + 8]; }
        #pragma unroll
        for (int nt = 0; nt < 8; nt++) {
            int gc = blockIdx.x * 128 + wn + nt * 8 + 2 * qid;
            float2 v0, v1;
            v0.x = acc[mt][nt][0]; v0.y = acc[mt][nt][1];
            v1.x = acc[mt][nt][2]; v1.y = acc[mt][nt][3];
            if (EPI == 3) { v0.x *= s0; v0.y *= s0; v1.x *= s1; v1.y *= s1; }
            if (EPI == 1 || EPI == 2) {
                float bx = bias[gc], by = bias[gc + 1];
                v0.x += bx; v0.y += by; v1.x += bx; v1.y += by;
                if (EPI == 1) {
                    v0.x = to_tf32(fmaxf(v0.x, 0.f)); v0.y = to_tf32(fmaxf(v0.y, 0.f));
                    v1.x = to_tf32(fmaxf(v1.x, 0.f)); v1.y = to_tf32(fmaxf(v1.y, 0.f));
                }
            }
            *(float2*)(C + (size_t)gr0 * Nd + gc)       = v0;
            *(float2*)(C + (size_t)(gr0 + 8) * Nd + gc) = v1;
        }
    }
}

// ---------------- fused gather + bias + relu + BN ----------------
// one warp per node: row = hs[node] + sum_{s in in(node)} hs[s]
// act = bn(relu(dinv[node]*row + b)), optionally tf32-rounded.
// Q4 = Nd/128 (float4s per lane).
template <int Q4, bool CVT>
__global__ __launch_bounds__(256) void gather_bn_k(
    const int* __restrict__ offs, const int* __restrict__ eidx,
    const float* __restrict__ hs, const float* __restrict__ dinv,
    const float* __restrict__ b,
    const float* __restrict__ g, const float* __restrict__ be,
    const float* __restrict__ m, const float* __restrict__ v,
    float* __restrict__ act, int Nd)
{
    int node = blockIdx.x * 8 + (threadIdx.x >> 5);
    int lane = threadIdx.x & 31;
    if (node >= Nn) return;

    const float4* self = (const float4*)(hs + (size_t)node * Nd);
    float4 acc[Q4];
    #pragma unroll
    for (int j = 0; j < Q4; j++) acc[j] = self[j * 32 + lane];

    int lo = offs[node], hi = offs[node + 1];
    for (int e = lo; e < hi; e++) {
        int s = eidx[e];
        const float4* hp = (const float4*)(hs + (size_t)s * Nd);
        #pragma unroll
        for (int j = 0; j < Q4; j++) {
            float4 t = hp[j * 32 + lane];
            acc[j].x += t.x; acc[j].y += t.y; acc[j].z += t.z; acc[j].w += t.w;
        }
    }

    float dv = dinv[node];
    float4* out = (float4*)(act + (size_t)node * Nd);
    #pragma unroll
    for (int j = 0; j < Q4; j++) {
        int c = (j * 32 + lane) * 4;
        float4 bb = *(const float4*)(b + c);
        float4 gg = *(const float4*)(g + c);
        float4 eb = *(const float4*)(be + c);
        float4 mm = *(const float4*)(m + c);
        float4 vv = *(const float4*)(v + c);
        float4 r;
        float y;
        y = fmaxf(dv * acc[j].x + bb.x, 0.f);
        r.x = gg.x * rsqrtf(vv.x + BN_EPS) * (y - mm.x) + eb.x;
        y = fmaxf(dv * acc[j].y + bb.y, 0.f);
        r.y = gg.y * rsqrtf(vv.y + BN_EPS) * (y - mm.y) + eb.y;
        y = fmaxf(dv * acc[j].z + bb.z, 0.f);
        r.z = gg.z * rsqrtf(vv.z + BN_EPS) * (y - mm.z) + eb.z;
        y = fmaxf(dv * acc[j].w + bb.w, 0.f);
        r.w = gg.w * rsqrtf(vv.w + BN_EPS) * (y - mm.w) + eb.w;
        if (CVT) {
            r.x = to_tf32(r.x); r.y = to_tf32(r.y);
            r.z = to_tf32(r.z); r.w = to_tf32(r.w);
        }
        out[j * 32 + lane] = r;
    }
}

// ---------------- mean pool ----------------
__device__ __forceinline__ int lower_bound_i(const int* a, int n, int key) {
    int lo = 0, hi = n;
    while (lo < hi) { int mid = (lo + hi) >> 1; if (a[mid] < key) lo = mid + 1; else hi = mid; }
    return lo;
}
__global__ void pool_k(const float* __restrict__ h, const int* __restrict__ batch,
                       float* __restrict__ pooled)
{
    int gph = blockIdx.x;
    __shared__ int s_lo, s_hi;
    if (threadIdx.x == 0) {
        s_lo = lower_bound_i(batch, Nn, gph);
        s_hi = lower_bound_i(batch, Nn, gph + 1);
    }
    __syncthreads();
    int lo = s_lo, hi = s_hi;
    int c = threadIdx.x;
    float acc = 0.f;
    for (int i = lo; i < hi; i++) acc += h[(size_t)i * DOUT + c];
    float cnt = (float)((hi - lo) > 0 ? (hi - lo) : 1);
    pooled[gph * DOUT + c] = to_tf32(acc / cnt);
}

// ---------------- launch ----------------
extern "C" void kernel_launch(void* const* d_in, const int* in_sizes, int n_in,
                              void* d_out, int out_size)
{
    const float* x   = (const float*)d_in[0];
    const int*   ei  = (const int*)  d_in[1];
    const int*   bat = (const int*)  d_in[2];
    const float* W1  = (const float*)d_in[3];
    const float* b1  = (const float*)d_in[4];
    const float* W2  = (const float*)d_in[5];
    const float* b2  = (const float*)d_in[6];
    const float* W3  = (const float*)d_in[7];
    const float* b3  = (const float*)d_in[8];
    const float* g1  = (const float*)d_in[9];
    const float* be1 = (const float*)d_in[10];
    const float* m1  = (const float*)d_in[11];
    const float* v1  = (const float*)d_in[12];
    const float* g2  = (const float*)d_in[13];
    const float* be2 = (const float*)d_in[14];
    const float* m2  = (const float*)d_in[15];
    const float* v2  = (const float*)d_in[16];
    const float* g3  = (const float*)d_in[17];
    const float* be3 = (const float*)d_in[18];
    const float* m3  = (const float*)d_in[19];
    const float* v3  = (const float*)d_in[20];
    const float* Wf1 = (const float*)d_in[21];
    const float* bf1 = (const float*)d_in[22];
    const float* Wf2 = (const float*)d_in[23];
    const float* bf2 = (const float*)d_in[24];

    const int* src = ei;
    const int* dst = ei + Ee;

    float *p_deg, *p_dinv, *p_hs, *p_act, *p_pool, *p_tmp;
    float4* p_bp;
    int *p_edeg, *p_offs, *p_cur, *p_eidx, *p_part;
    cudaGetSymbolAddress((void**)&p_deg,  g_deg);
    cudaGetSymbolAddress((void**)&p_dinv, g_dinv);
    cudaGetSymbolAddress((void**)&p_hs,   g_hs);
    cudaGetSymbolAddress((void**)&p_act,  g_act);
    cudaGetSymbolAddress((void**)&p_pool, g_pool);
    cudaGetSymbolAddress((void**)&p_tmp,  g_tmp);
    cudaGetSymbolAddress((void**)&p_bp,   g_bpack);
    cudaGetSymbolAddress((void**)&p_edeg, g_edeg);
    cudaGetSymbolAddress((void**)&p_offs, g_offs);
    cudaGetSymbolAddress((void**)&p_cur,  g_cur);
    cudaGetSymbolAddress((void**)&p_eidx, g_eidx);
    cudaGetSymbolAddress((void**)&p_part, g_part);

    const int SMEM = 65536;
    cudaFuncSetAttribute(tgemm_k<3>, cudaFuncAttributeMaxDynamicSharedMemorySize, SMEM);
    cudaFuncSetAttribute(tgemm_k<1>, cudaFuncAttributeMaxDynamicSharedMemorySize, SMEM);
    cudaFuncSetAttribute(tgemm_k<2>, cudaFuncAttributeMaxDynamicSharedMemorySize, SMEM);

    // degree / dinv / CSR
    deg_init_k<<<Nn / 256, 256>>>(p_deg, p_edeg);
    deg_acc_k <<<Ee / 256, 256>>>(dst, p_deg, p_edeg);
    dinv_k    <<<Nn / 256, 256>>>(p_deg, p_dinv);
    scan1_k<<<256, 512>>>(p_edeg, p_offs, p_part);
    scan2_k<<<1, 256>>>(p_part);
    scan3_k<<<Nn / 256, 256>>>(p_offs, p_cur, p_part);
    fill_k <<<Ee / 256, 256>>>(src, dst, p_cur, p_eidx);

    // layer-1 A: tf32-rounded copy of x
    cvt_copy_k<<<(Nn * DIN / 4) / 256, 256>>>((const float4*)x, (float4*)p_act, Nn * DIN / 4);

    // ---- layer 1 ----
    packB_k<<<(DIN/32)*(DH/128)*1024/256, 256>>>(W1, p_bp, DIN, DH);
    tgemm_k<3><<<dim3(DH/128, Nn/128), 256, SMEM>>>(p_act, p_bp, nullptr, p_dinv, p_hs, Nn, DIN, DH);
    gather_bn_k<4, true><<<Nn / 8, 256>>>(p_offs, p_eidx, p_hs, p_dinv, b1, g1, be1, m1, v1, p_act, DH);

    // ---- layer 2 ----
    packB_k<<<(DH/32)*(DH/128)*1024/256, 256>>>(W2, p_bp, DH, DH);
    tgemm_k<3><<<dim3(DH/128, Nn/128), 256, SMEM>>>(p_act, p_bp, nullptr, p_dinv, p_hs, Nn, DH, DH);
    gather_bn_k<4, true><<<Nn / 8, 256>>>(p_offs, p_eidx, p_hs, p_dinv, b2, g2, be2, m2, v2, p_act, DH);

    // ---- layer 3 ----
    packB_k<<<(DH/32)*(DOUT/128)*1024/256, 256>>>(W3, p_bp, DH, DOUT);
    tgemm_k<3><<<dim3(DOUT/128, Nn/128), 256, SMEM>>>(p_act, p_bp, nullptr, p_dinv, p_hs, Nn, DH, DOUT);
    gather_bn_k<2, false><<<Nn / 8, 256>>>(p_offs, p_eidx, p_hs, p_dinv, b3, g3, be3, m3, v3, p_act, DOUT);

    // ---- pool + MLP head ----
    pool_k<<<Gg, DOUT>>>(p_act, bat, p_pool);
    packB_k<<<(DOUT/32)*(DOUT/128)*1024/256, 256>>>(Wf1, p_bp, DOUT, DOUT);
    tgemm_k<1><<<dim3(DOUT/128, Gg/128), 256, SMEM>>>(p_pool, p_bp, bf1, nullptr, p_tmp, Gg, DOUT, DOUT);
    packB_k<<<(DOUT/32)*(DOUT/128)*1024/256, 256>>>(Wf2, p_bp, DOUT, DOUT);
    tgemm_k<2><<<dim3(DOUT/128, Gg/128), 256, SMEM>>>(p_tmp, p_bp, bf2, nullptr, (float*)d_out, Gg, DOUT, DOUT);
}

// round 6
// speedup vs baseline: 3.3961x; 1.1219x over previous
#include <cuda_runtime.h>
#include <cstddef>

#define Nn   131072
#define Ee   524288
#define Gg   4096
#define DIN  128
#define DH   512
#define DOUT 256
#define BN_EPS 1e-5f

// ---------------- scratch ----------------
__device__ float g_deg [Nn];
__device__ float g_dinv[Nn];
__device__ float g_hs  [(size_t)Nn * DH];
__device__ float g_act [(size_t)Nn * DH];
__device__ float g_pool[Gg * DOUT];
__device__ float g_tmp [Gg * DOUT];
__device__ float4 g_bpack[65536];
__device__ int   g_edeg [Nn];
__device__ int   g_offs [Nn + 1];
__device__ int   g_cur  [Nn];
__device__ int   g_eidx [Ee];
__device__ int   g_part [256];

// ---------------- degree / norm ----------------
__global__ void deg_init_k(float* deg, int* edeg) {
    int i = blockIdx.x * blockDim.x + threadIdx.x;
    if (i < Nn) { deg[i] = 1.0f; edeg[i] = 0; }
}
__global__ void deg_acc_k(const int* __restrict__ dst, float* deg, int* edeg) {
    int e = blockIdx.x * blockDim.x + threadIdx.x;
    if (e < Ee) { int d = dst[e]; atomicAdd(&deg[d], 1.0f); atomicAdd(&edeg[d], 1); }
}
__global__ void dinv_k(const float* __restrict__ deg, float* dinv) {
    int i = blockIdx.x * blockDim.x + threadIdx.x;
    if (i < Nn) dinv[i] = rsqrtf(deg[i]);
}

// ---------------- CSR build ----------------
__global__ void scan1_k(const int* __restrict__ in, int* out, int* part) {
    __shared__ int s[512];
    int b = blockIdx.x, t = threadIdx.x;
    int v = in[b * 512 + t];
    s[t] = v; __syncthreads();
    #pragma unroll
    for (int o = 1; o < 512; o <<= 1) {
        int x = (t >= o) ? s[t - o] : 0;
        __syncthreads();
        s[t] += x;
        __syncthreads();
    }
    out[b * 512 + t] = s[t] - v;
    if (t == 511) part[b] = s[t];
}
__global__ void scan2_k(int* part) {
    __shared__ int s[256];
    int t = threadIdx.x;
    int v = part[t];
    s[t] = v; __syncthreads();
    #pragma unroll
    for (int o = 1; o < 256; o <<= 1) {
        int x = (t >= o) ? s[t - o] : 0;
        __syncthreads();
        s[t] += x;
        __syncthreads();
    }
    part[t] = s[t] - v;
}
__global__ void scan3_k(int* offs, int* cur, const int* __restrict__ part) {
    int i = blockIdx.x * blockDim.x + threadIdx.x;
    if (i < Nn) {
        int o = offs[i] + part[i >> 9];
        offs[i] = o;
        cur[i] = o;
    }
    if (i == 0) offs[Nn] = Ee;
}
__global__ void fill_k(const int* __restrict__ src, const int* __restrict__ dst,
                       int* cur, int* eidx) {
    int e = blockIdx.x * blockDim.x + threadIdx.x;
    if (e >= Ee) return;
    int d = dst[e];
    int pos = atomicAdd(&cur[d], 1);
    eidx[pos] = src[e];
}

// ---------------- tf32 helpers ----------------
__device__ __forceinline__ float to_tf32(float x) {
    unsigned u;
    asm("cvt.rna.tf32.f32 %0, %1;" : "=r"(u) : "f"(x));
    return __uint_as_float(u);
}
__device__ __forceinline__ void mma_tf32(float* d, const float* a, const float* b) {
    asm volatile(
        "mma.sync.aligned.m16n8k8.row.col.f32.tf32.tf32.f32 "
        "{%0,%1,%2,%3}, {%4,%5,%6,%7}, {%8,%9}, {%0,%1,%2,%3};"
        : "+f"(d[0]), "+f"(d[1]), "+f"(d[2]), "+f"(d[3])
        : "r"(__float_as_uint(a[0])), "r"(__float_as_uint(a[1])),
          "r"(__float_as_uint(a[2])), "r"(__float_as_uint(a[3])),
          "r"(__float_as_uint(b[0])), "r"(__float_as_uint(b[1])));
}
__device__ __forceinline__ void cp_async16(void* smem, const void* gmem) {
    unsigned s = (unsigned)__cvta_generic_to_shared(smem);
    asm volatile("cp.async.cg.shared.global [%0], [%1], 16;" :: "r"(s), "l"(gmem));
}

// ---------------- xs = x * dinv[row]  (fp32) ----------------
__global__ void cvt_scale_k(const float4* __restrict__ in, const float* __restrict__ dinv,
                            float4* __restrict__ out, int q, int n4) {
    int i = blockIdx.x * blockDim.x + threadIdx.x;
    if (i >= n4) return;
    float dv = dinv[i / q];
    float4 v = in[i];
    v.x *= dv; v.y *= dv; v.z *= dv; v.w *= dv;
    out[i] = v;
}

// ---------------- pack B ----------------
__global__ void packB_k(const float* __restrict__ W, float4* __restrict__ out, int K, int Nd) {
    int idx = blockIdx.x * blockDim.x + threadIdx.x;
    int total = (K >> 5) * (Nd >> 7) * 1024;
    if (idx >= total) return;
    int q = idx & 3, grp = (idx >> 2) & 7, ntpl = (idx >> 5) & 7, ks = (idx >> 8) & 3;
    int tile = idx >> 10;
    int nb = Nd >> 7;
    int k0 = (tile / nb) * 32, bxn = tile % nb;
    int n0 = bxn * 128 + ntpl * 16 + grp;
    int kr = k0 + ks * 8 + q;
    float4 v;
    v.x = to_tf32(W[(size_t)kr * Nd + n0]);
    v.y = to_tf32(W[(size_t)(kr + 4) * Nd + n0]);
    v.z = to_tf32(W[(size_t)kr * Nd + n0 + 8]);
    v.w = to_tf32(W[(size_t)(kr + 4) * Nd + n0 + 8]);
    out[idx] = v;
}

// ---------------- tf32 tensor GEMM, prepacked B, double-buffered ----------------
// EPI: 1 +bias+relu+cvt | 2 +bias | 3 scale-by-dinv[row] | 4 +bias+relu+BN+cvt
template <int EPI>
__global__ __launch_bounds__(256, 2) void tgemm_k(
    const float* __restrict__ A, const float4* __restrict__ Bp,
    const float* __restrict__ bias, const float* __restrict__ dinv,
    const float* __restrict__ bg, const float* __restrict__ bbe,
    const float* __restrict__ bm, const float* __restrict__ bv,
    float* __restrict__ C,
    int M, int K, int Nd)
{
    extern __shared__ float4 smem4[];
    float4* As = smem4;
    float4* Bs = smem4 + 2048;

    const int t    = threadIdx.x;
    const int warp = t >> 5, lane = t & 31;
    const int wm = (warp >> 1) * 32;
    const int wn = (warp & 1) * 64;
    const int grp = lane >> 2, qid = lane & 3;
    const int mt0 = (warp >> 1) * 2, mt1 = mt0 + 1;
    const int nb = Nd >> 7;
    const int T = K >> 5;

    const size_t row0 = (size_t)blockIdx.y * 128;
    const float* Ablk = A + row0 * K;

    const int fa_ks = t & 3, fa_g = (t >> 2) & 7, fa_mt = t >> 5;
    const float* ArowLo = Ablk + (size_t)(fa_mt * 16 + fa_g) * K + fa_ks * 8;
    const float* ArowHi = ArowLo + (size_t)8 * K;
    const int fa_idx = fa_ks * 256 + fa_mt * 32 + fa_g * 4;

    float acc[2][8][4];
    #pragma unroll
    for (int i = 0; i < 2; i++)
        #pragma unroll
        for (int j = 0; j < 8; j++)
            #pragma unroll
            for (int l = 0; l < 4; l++) acc[i][j][l] = 0.f;

    float4 ra0, ra1, rb0, rb1;
    ra0 = *(const float4*)(ArowLo);
    ra1 = *(const float4*)(ArowLo + 4);
    rb0 = *(const float4*)(ArowHi);
    rb1 = *(const float4*)(ArowHi + 4);

    {
        const float4* bsrc = Bp + ((size_t)blockIdx.x) * 1024 + t * 4;
        #pragma unroll
        for (int j = 0; j < 4; j++) cp_async16(&Bs[t * 4 + j], bsrc + j);
        asm volatile("cp.async.commit_group;");
        const float* qa0 = &ra0.x; const float* qa1 = &ra1.x;
        const float* qb0 = &rb0.x; const float* qb1 = &rb1.x;
        #pragma unroll
        for (int q = 0; q < 4; q++)
            As[fa_idx + (q ^ fa_ks)] = make_float4(qa0[q], qb0[q], qa1[q], qb1[q]);
        asm volatile("cp.async.wait_group 0;");
    }
    __syncthreads();

    for (int i = 0; i < T; i++) {
        const int st = i & 1;
        const bool more = (i + 1 < T);
        if (more) {
            const int kn = (i + 1) * 32;
            ra0 = *(const float4*)(ArowLo + kn);
            ra1 = *(const float4*)(ArowLo + kn + 4);
            rb0 = *(const float4*)(ArowHi + kn);
            rb1 = *(const float4*)(ArowHi + kn + 4);
            const float4* bsrc = Bp + ((size_t)(i + 1) * nb + blockIdx.x) * 1024 + t * 4;
            float4* bdst = &Bs[(1 - st) * 1024 + t * 4];
            #pragma unroll
            for (int j = 0; j < 4; j++) cp_async16(bdst + j, bsrc + j);
            asm volatile("cp.async.commit_group;");
        }

        const float4* Ast = &As[st * 1024];
        const float4* Bst = &Bs[st * 1024];
        #pragma unroll
        for (int ks = 0; ks < 4; ks++) {
            float4 af0 = Ast[ks * 256 + mt0 * 32 + grp * 4 + (qid ^ ks)];
            float4 af1 = Ast[ks * 256 + mt1 * 32 + grp * 4 + (qid ^ ks)];
            float4 bfp[4];
            #pragma unroll
            for (int p = 0; p < 4; p++) {
                int ntpl = (wn >> 4) + p;
                bfp[p] = Bst[ks * 256 + ntpl * 32 + grp * 4 + qid];
            }
            #pragma unroll
            for (int p = 0; p < 4; p++) {
                mma_tf32(acc[0][2 * p],     &af0.x, &bfp[p].x);
                mma_tf32(acc[0][2 * p + 1], &af0.x, &bfp[p].z);
                mma_tf32(acc[1][2 * p],     &af1.x, &bfp[p].x);
                mma_tf32(acc[1][2 * p + 1], &af1.x, &bfp[p].z);
            }
        }

        if (more) {
            float4* Adst = &As[(1 - st) * 1024];
            const float* qa0 = &ra0.x; const float* qa1 = &ra1.x;
            const float* qb0 = &rb0.x; const float* qb1 = &rb1.x;
            #pragma unroll
            for (int q = 0; q < 4; q++)
                Adst[fa_idx + (q ^ fa_ks)] = make_float4(qa0[q], qb0[q], qa1[q], qb1[q]);
            asm volatile("cp.async.wait_group 0;");
        }
        __syncthreads();
    }

    #pragma unroll
    for (int mt = 0; mt < 2; mt++) {
        const int gr0 = (int)row0 + wm + mt * 16 + grp;
        float s0 = 1.f, s1 = 1.f;
        if (EPI == 3) { s0 = dinv[gr0]; s1 = dinv[gr0 + 8]; }
        #pragma unroll
        for (int nt = 0; nt < 8; nt++) {
            int gc = blockIdx.x * 128 + wn + nt * 8 + 2 * qid;
            float2 v0, v1;
            v0.x = acc[mt][nt][0]; v0.y = acc[mt][nt][1];
            v1.x = acc[mt][nt][2]; v1.y = acc[mt][nt][3];
            if (EPI == 3) { v0.x *= s0; v0.y *= s0; v1.x *= s1; v1.y *= s1; }
            if (EPI == 1 || EPI == 2 || EPI == 4) {
                float bx = bias[gc], by = bias[gc + 1];
                v0.x += bx; v0.y += by; v1.x += bx; v1.y += by;
                if (EPI == 1) {
                    v0.x = to_tf32(fmaxf(v0.x, 0.f)); v0.y = to_tf32(fmaxf(v0.y, 0.f));
                    v1.x = to_tf32(fmaxf(v1.x, 0.f)); v1.y = to_tf32(fmaxf(v1.y, 0.f));
                }
                if (EPI == 4) {
                    float scx = bg[gc]     * rsqrtf(bv[gc]     + BN_EPS);
                    float scy = bg[gc + 1] * rsqrtf(bv[gc + 1] + BN_EPS);
                    float mx = bm[gc], my = bm[gc + 1];
                    float ex = bbe[gc], ey = bbe[gc + 1];
                    v0.x = to_tf32(scx * (fmaxf(v0.x, 0.f) - mx) + ex);
                    v0.y = to_tf32(scy * (fmaxf(v0.y, 0.f) - my) + ey);
                    v1.x = to_tf32(scx * (fmaxf(v1.x, 0.f) - mx) + ex);
                    v1.y = to_tf32(scy * (fmaxf(v1.y, 0.f) - my) + ey);
                }
            }
            *(float2*)(C + (size_t)gr0 * Nd + gc)       = v0;
            *(float2*)(C + (size_t)(gr0 + 8) * Nd + gc) = v1;
        }
    }
}

// ---------------- layer-1 input aggregation: agg = tf32(dinv[n]*(xs[n] + sum xs[src])) ----------------
__global__ __launch_bounds__(256) void gather_agg_k(
    const int* __restrict__ offs, const int* __restrict__ eidx,
    const float* __restrict__ xs, const float* __restrict__ dinv,
    float* __restrict__ agg)
{
    int node = blockIdx.x * 8 + (threadIdx.x >> 5);
    int lane = threadIdx.x & 31;
    if (node >= Nn) return;

    float4 acc = ((const float4*)(xs + (size_t)node * DIN))[lane];
    int lo = offs[node], hi = offs[node + 1];
    for (int e = lo; e < hi; e++) {
        int s = eidx[e];
        float4 t = ((const float4*)(xs + (size_t)s * DIN))[lane];
        acc.x += t.x; acc.y += t.y; acc.z += t.z; acc.w += t.w;
    }
    float dv = dinv[node];
    acc.x = to_tf32(dv * acc.x); acc.y = to_tf32(dv * acc.y);
    acc.z = to_tf32(dv * acc.z); acc.w = to_tf32(dv * acc.w);
    ((float4*)(agg + (size_t)node * DIN))[lane] = acc;
}

// ---------------- fused gather + bias + relu + BN (layers 2,3) ----------------
template <int Q4, bool CVT>
__global__ __launch_bounds__(256) void gather_bn_k(
    const int* __restrict__ offs, const int* __restrict__ eidx,
    const float* __restrict__ hs, const float* __restrict__ dinv,
    const float* __restrict__ b,
    const float* __restrict__ g, const float* __restrict__ be,
    const float* __restrict__ m, const float* __restrict__ v,
    float* __restrict__ act, int Nd)
{
    int node = blockIdx.x * 8 + (threadIdx.x >> 5);
    int lane = threadIdx.x & 31;
    if (node >= Nn) return;

    const float4* self = (const float4*)(hs + (size_t)node * Nd);
    float4 acc[Q4];
    #pragma unroll
    for (int j = 0; j < Q4; j++) acc[j] = self[j * 32 + lane];

    int lo = offs[node], hi = offs[node + 1];
    for (int e = lo; e < hi; e++) {
        int s = eidx[e];
        const float4* hp = (const float4*)(hs + (size_t)s * Nd);
        #pragma unroll
        for (int j = 0; j < Q4; j++) {
            float4 t = hp[j * 32 + lane];
            acc[j].x += t.x; acc[j].y += t.y; acc[j].z += t.z; acc[j].w += t.w;
        }
    }

    float dv = dinv[node];
    float4* out = (float4*)(act + (size_t)node * Nd);
    #pragma unroll
    for (int j = 0; j < Q4; j++) {
        int c = (j * 32 + lane) * 4;
        float4 bb = *(const float4*)(b + c);
        float4 gg = *(const float4*)(g + c);
        float4 eb = *(const float4*)(be + c);
        float4 mm = *(const float4*)(m + c);
        float4 vv = *(const float4*)(v + c);
        float4 r;
        float y;
        y = fmaxf(dv * acc[j].x + bb.x, 0.f);
        r.x = gg.x * rsqrtf(vv.x + BN_EPS) * (y - mm.x) + eb.x;
        y = fmaxf(dv * acc[j].y + bb.y, 0.f);
        r.y = gg.y * rsqrtf(vv.y + BN_EPS) * (y - mm.y) + eb.y;
        y = fmaxf(dv * acc[j].z + bb.z, 0.f);
        r.z = gg.z * rsqrtf(vv.z + BN_EPS) * (y - mm.z) + eb.z;
        y = fmaxf(dv * acc[j].w + bb.w, 0.f);
        r.w = gg.w * rsqrtf(vv.w + BN_EPS) * (y - mm.w) + eb.w;
        if (CVT) {
            r.x = to_tf32(r.x); r.y = to_tf32(r.y);
            r.z = to_tf32(r.z); r.w = to_tf32(r.w);
        }
        out[j * 32 + lane] = r;
    }
}

// ---------------- mean pool ----------------
__device__ __forceinline__ int lower_bound_i(const int* a, int n, int key) {
    int lo = 0, hi = n;
    while (lo < hi) { int mid = (lo + hi) >> 1; if (a[mid] < key) lo = mid + 1; else hi = mid; }
    return lo;
}
__global__ void pool_k(const float* __restrict__ h, const int* __restrict__ batch,
                       float* __restrict__ pooled)
{
    int gph = blockIdx.x;
    __shared__ int s_lo, s_hi;
    if (threadIdx.x == 0) {
        s_lo = lower_bound_i(batch, Nn, gph);
        s_hi = lower_bound_i(batch, Nn, gph + 1);
    }
    __syncthreads();
    int lo = s_lo, hi = s_hi;
    int c = threadIdx.x;
    float acc = 0.f;
    for (int i = lo; i < hi; i++) acc += h[(size_t)i * DOUT + c];
    float cnt = (float)((hi - lo) > 0 ? (hi - lo) : 1);
    pooled[gph * DOUT + c] = to_tf32(acc / cnt);
}

// ---------------- launch ----------------
extern "C" void kernel_launch(void* const* d_in, const int* in_sizes, int n_in,
                              void* d_out, int out_size)
{
    const float* x   = (const float*)d_in[0];
    const int*   ei  = (const int*)  d_in[1];
    const int*   bat = (const int*)  d_in[2];
    const float* W1  = (const float*)d_in[3];
    const float* b1  = (const float*)d_in[4];
    const float* W2  = (const float*)d_in[5];
    const float* b2  = (const float*)d_in[6];
    const float* W3  = (const float*)d_in[7];
    const float* b3  = (const float*)d_in[8];
    const float* g1  = (const float*)d_in[9];
    const float* be1 = (const float*)d_in[10];
    const float* m1  = (const float*)d_in[11];
    const float* v1  = (const float*)d_in[12];
    const float* g2  = (const float*)d_in[13];
    const float* be2 = (const float*)d_in[14];
    const float* m2  = (const float*)d_in[15];
    const float* v2  = (const float*)d_in[16];
    const float* g3  = (const float*)d_in[17];
    const float* be3 = (const float*)d_in[18];
    const float* m3  = (const float*)d_in[19];
    const float* v3  = (const float*)d_in[20];
    const float* Wf1 = (const float*)d_in[21];
    const float* bf1 = (const float*)d_in[22];
    const float* Wf2 = (const float*)d_in[23];
    const float* bf2 = (const float*)d_in[24];

    const int* src = ei;
    const int* dst = ei + Ee;

    float *p_deg, *p_dinv, *p_hs, *p_act, *p_pool, *p_tmp;
    float4* p_bp;
    int *p_edeg, *p_offs, *p_cur, *p_eidx, *p_part;
    cudaGetSymbolAddress((void**)&p_deg,  g_deg);
    cudaGetSymbolAddress((void**)&p_dinv, g_dinv);
    cudaGetSymbolAddress((void**)&p_hs,   g_hs);
    cudaGetSymbolAddress((void**)&p_act,  g_act);
    cudaGetSymbolAddress((void**)&p_pool, g_pool);
    cudaGetSymbolAddress((void**)&p_tmp,  g_tmp);
    cudaGetSymbolAddress((void**)&p_bp,   g_bpack);
    cudaGetSymbolAddress((void**)&p_edeg, g_edeg);
    cudaGetSymbolAddress((void**)&p_offs, g_offs);
    cudaGetSymbolAddress((void**)&p_cur,  g_cur);
    cudaGetSymbolAddress((void**)&p_eidx, g_eidx);
    cudaGetSymbolAddress((void**)&p_part, g_part);

    const int SMEM = 65536;
    cudaFuncSetAttribute(tgemm_k<1>, cudaFuncAttributeMaxDynamicSharedMemorySize, SMEM);
    cudaFuncSetAttribute(tgemm_k<2>, cudaFuncAttributeMaxDynamicSharedMemorySize, SMEM);
    cudaFuncSetAttribute(tgemm_k<3>, cudaFuncAttributeMaxDynamicSharedMemorySize, SMEM);
    cudaFuncSetAttribute(tgemm_k<4>, cudaFuncAttributeMaxDynamicSharedMemorySize, SMEM);

    // degree / dinv / CSR
    deg_init_k<<<Nn / 256, 256>>>(p_deg, p_edeg);
    deg_acc_k <<<Ee / 256, 256>>>(dst, p_deg, p_edeg);
    dinv_k    <<<Nn / 256, 256>>>(p_deg, p_dinv);
    scan1_k<<<256, 512>>>(p_edeg, p_offs, p_part);
    scan2_k<<<1, 256>>>(p_part);
    scan3_k<<<Nn / 256, 256>>>(p_offs, p_cur, p_part);
    fill_k <<<Ee / 256, 256>>>(src, dst, p_cur, p_eidx);

    // ---- layer 1: aggregate-then-GEMM (Âx)W1 with fused BN epilogue ----
    cvt_scale_k<<<(Nn * DIN / 4) / 256, 256>>>((const float4*)x, p_dinv, (float4*)p_act, DIN / 4, Nn * DIN / 4);
    gather_agg_k<<<Nn / 8, 256>>>(p_offs, p_eidx, p_act, p_dinv, p_hs);
    packB_k<<<(DIN/32)*(DH/128)*1024/256, 256>>>(W1, p_bp, DIN, DH);
    tgemm_k<4><<<dim3(DH/128, Nn/128), 256, SMEM>>>(p_hs, p_bp, b1, nullptr, g1, be1, m1, v1, p_act, Nn, DIN, DH);

    // ---- layer 2 ----
    packB_k<<<(DH/32)*(DH/128)*1024/256, 256>>>(W2, p_bp, DH, DH);
    tgemm_k<3><<<dim3(DH/128, Nn/128), 256, SMEM>>>(p_act, p_bp, nullptr, p_dinv, nullptr, nullptr, nullptr, nullptr, p_hs, Nn, DH, DH);
    gather_bn_k<4, true><<<Nn / 8, 256>>>(p_offs, p_eidx, p_hs, p_dinv, b2, g2, be2, m2, v2, p_act, DH);

    // ---- layer 3 ----
    packB_k<<<(DH/32)*(DOUT/128)*1024/256, 256>>>(W3, p_bp, DH, DOUT);
    tgemm_k<3><<<dim3(DOUT/128, Nn/128), 256, SMEM>>>(p_act, p_bp, nullptr, p_dinv, nullptr, nullptr, nullptr, nullptr, p_hs, Nn, DH, DOUT);
    gather_bn_k<2, false><<<Nn / 8, 256>>>(p_offs, p_eidx, p_hs, p_dinv, b3, g3, be3, m3, v3, p_act, DOUT);

    // ---- pool + MLP head ----
    pool_k<<<Gg, DOUT>>>(p_act, bat, p_pool);
    packB_k<<<(DOUT/32)*(DOUT/128)*1024/256, 256>>>(Wf1, p_bp, DOUT, DOUT);
    tgemm_k<1><<<dim3(DOUT/128, Gg/128), 256, SMEM>>>(p_pool, p_bp, bf1, nullptr, nullptr, nullptr, nullptr, nullptr, p_tmp, Gg, DOUT, DOUT);
    packB_k<<<(DOUT/32)*(DOUT/128)*1024/256, 256>>>(Wf2, p_bp, DOUT, DOUT);
    tgemm_k<2><<<dim3(DOUT/128, Gg/128), 256, SMEM>>>(p_tmp, p_bp, bf2, nullptr, nullptr, nullptr, nullptr, nullptr, (float*)d_out, Gg, DOUT, DOUT);
}

// round 7
// speedup vs baseline: 3.6236x; 1.0670x over previous
#include <cuda_runtime.h>
#include <cstddef>

#define Nn   131072
#define Ee   524288
#define Gg   4096
#define DIN  128
#define DH   512
#define DOUT 256
#define BN_EPS 1e-5f

// ---------------- scratch ----------------
__device__ float g_deg [Nn];
__device__ float g_dinv[Nn];
__device__ float g_hs  [(size_t)Nn * DH];
__device__ float g_act [(size_t)Nn * DH];
__device__ float g_pool[Gg * DOUT];
__device__ float g_tmp [Gg * DOUT];
__device__ float4 g_bpack[65536];
__device__ int   g_edeg [Nn];
__device__ int   g_offs [Nn + 1];
__device__ int   g_cur  [Nn];
__device__ int   g_eidx [Ee];
__device__ int   g_part [256];

// ---------------- degree / norm ----------------
__global__ void deg_init_k(float* deg, int* edeg) {
    int i = blockIdx.x * blockDim.x + threadIdx.x;
    if (i < Nn) { deg[i] = 1.0f; edeg[i] = 0; }
}
__global__ void deg_acc_k(const int* __restrict__ dst, float* deg, int* edeg) {
    int e = blockIdx.x * blockDim.x + threadIdx.x;
    if (e < Ee) { int d = dst[e]; atomicAdd(&deg[d], 1.0f); atomicAdd(&edeg[d], 1); }
}
__global__ void dinv_k(const float* __restrict__ deg, float* dinv) {
    int i = blockIdx.x * blockDim.x + threadIdx.x;
    if (i < Nn) dinv[i] = rsqrtf(deg[i]);
}

// ---------------- CSR build ----------------
__global__ void scan1_k(const int* __restrict__ in, int* out, int* part) {
    __shared__ int s[512];
    int b = blockIdx.x, t = threadIdx.x;
    int v = in[b * 512 + t];
    s[t] = v; __syncthreads();
    #pragma unroll
    for (int o = 1; o < 512; o <<= 1) {
        int x = (t >= o) ? s[t - o] : 0;
        __syncthreads();
        s[t] += x;
        __syncthreads();
    }
    out[b * 512 + t] = s[t] - v;
    if (t == 511) part[b] = s[t];
}
__global__ void scan2_k(int* part) {
    __shared__ int s[256];
    int t = threadIdx.x;
    int v = part[t];
    s[t] = v; __syncthreads();
    #pragma unroll
    for (int o = 1; o < 256; o <<= 1) {
        int x = (t >= o) ? s[t - o] : 0;
        __syncthreads();
        s[t] += x;
        __syncthreads();
    }
    part[t] = s[t] - v;
}
__global__ void scan3_k(int* offs, int* cur, const int* __restrict__ part) {
    int i = blockIdx.x * blockDim.x + threadIdx.x;
    if (i < Nn) {
        int o = offs[i] + part[i >> 9];
        offs[i] = o;
        cur[i] = o;
    }
    if (i == 0) offs[Nn] = Ee;
}
__global__ void fill_k(const int* __restrict__ src, const int* __restrict__ dst,
                       int* cur, int* eidx) {
    int e = blockIdx.x * blockDim.x + threadIdx.x;
    if (e >= Ee) return;
    int d = dst[e];
    int pos = atomicAdd(&cur[d], 1);
    eidx[pos] = src[e];
}

// ---------------- tf32 helpers ----------------
__device__ __forceinline__ float to_tf32(float x) {
    unsigned u;
    asm("cvt.rna.tf32.f32 %0, %1;" : "=r"(u) : "f"(x));
    return __uint_as_float(u);
}
__device__ __forceinline__ void mma_tf32(float* d, const float* a, const float* b) {
    asm volatile(
        "mma.sync.aligned.m16n8k8.row.col.f32.tf32.tf32.f32 "
        "{%0,%1,%2,%3}, {%4,%5,%6,%7}, {%8,%9}, {%0,%1,%2,%3};"
        : "+f"(d[0]), "+f"(d[1]), "+f"(d[2]), "+f"(d[3])
        : "r"(__float_as_uint(a[0])), "r"(__float_as_uint(a[1])),
          "r"(__float_as_uint(a[2])), "r"(__float_as_uint(a[3])),
          "r"(__float_as_uint(b[0])), "r"(__float_as_uint(b[1])));
}
__device__ __forceinline__ void cp_async16(void* smem, const void* gmem) {
    unsigned s = (unsigned)__cvta_generic_to_shared(smem);
    asm volatile("cp.async.cg.shared.global [%0], [%1], 16;" :: "r"(s), "l"(gmem));
}

// ---------------- pack B ----------------
__global__ void packB_k(const float* __restrict__ W, float4* __restrict__ out, int K, int Nd) {
    int idx = blockIdx.x * blockDim.x + threadIdx.x;
    int total = (K >> 5) * (Nd >> 7) * 1024;
    if (idx >= total) return;
    int q = idx & 3, grp = (idx >> 2) & 7, ntpl = (idx >> 5) & 7, ks = (idx >> 8) & 3;
    int tile = idx >> 10;
    int nb = Nd >> 7;
    int k0 = (tile / nb) * 32, bxn = tile % nb;
    int n0 = bxn * 128 + ntpl * 16 + grp;
    int kr = k0 + ks * 8 + q;
    float4 v;
    v.x = to_tf32(W[(size_t)kr * Nd + n0]);
    v.y = to_tf32(W[(size_t)(kr + 4) * Nd + n0]);
    v.z = to_tf32(W[(size_t)kr * Nd + n0 + 8]);
    v.w = to_tf32(W[(size_t)(kr + 4) * Nd + n0 + 8]);
    out[idx] = v;
}

// ---------------- tf32 tensor GEMM, prepacked B, double-buffered ----------------
// EPI: 1 +bias+relu+cvt | 2 +bias | 3 scale-by-dinv[row] | 4 +bias+relu+BN+cvt
template <int EPI>
__global__ __launch_bounds__(256, 2) void tgemm_k(
    const float* __restrict__ A, const float4* __restrict__ Bp,
    const float* __restrict__ bias, const float* __restrict__ dinv,
    const float* __restrict__ bg, const float* __restrict__ bbe,
    const float* __restrict__ bm, const float* __restrict__ bv,
    float* __restrict__ C,
    int M, int K, int Nd)
{
    extern __shared__ float4 smem4[];
    float4* As = smem4;
    float4* Bs = smem4 + 2048;

    const int t    = threadIdx.x;
    const int warp = t >> 5, lane = t & 31;
    const int wm = (warp >> 1) * 32;
    const int wn = (warp & 1) * 64;
    const int grp = lane >> 2, qid = lane & 3;
    const int mt0 = (warp >> 1) * 2, mt1 = mt0 + 1;
    const int nb = Nd >> 7;
    const int T = K >> 5;

    const size_t row0 = (size_t)blockIdx.y * 128;
    const float* Ablk = A + row0 * K;

    const int fa_ks = t & 3, fa_g = (t >> 2) & 7, fa_mt = t >> 5;
    const float* ArowLo = Ablk + (size_t)(fa_mt * 16 + fa_g) * K + fa_ks * 8;
    const float* ArowHi = ArowLo + (size_t)8 * K;
    const int fa_idx = fa_ks * 256 + fa_mt * 32 + fa_g * 4;

    float acc[2][8][4];
    #pragma unroll
    for (int i = 0; i < 2; i++)
        #pragma unroll
        for (int j = 0; j < 8; j++)
            #pragma unroll
            for (int l = 0; l < 4; l++) acc[i][j][l] = 0.f;

    float4 ra0, ra1, rb0, rb1;
    ra0 = *(const float4*)(ArowLo);
    ra1 = *(const float4*)(ArowLo + 4);
    rb0 = *(const float4*)(ArowHi);
    rb1 = *(const float4*)(ArowHi + 4);

    {
        const float4* bsrc = Bp + ((size_t)blockIdx.x) * 1024 + t * 4;
        #pragma unroll
        for (int j = 0; j < 4; j++) cp_async16(&Bs[t * 4 + j], bsrc + j);
        asm volatile("cp.async.commit_group;");
        const float* qa0 = &ra0.x; const float* qa1 = &ra1.x;
        const float* qb0 = &rb0.x; const float* qb1 = &rb1.x;
        #pragma unroll
        for (int q = 0; q < 4; q++)
            As[fa_idx + (q ^ fa_ks)] = make_float4(qa0[q], qb0[q], qa1[q], qb1[q]);
        asm volatile("cp.async.wait_group 0;");
    }
    __syncthreads();

    for (int i = 0; i < T; i++) {
        const int st = i & 1;
        const bool more = (i + 1 < T);
        if (more) {
            const int kn = (i + 1) * 32;
            ra0 = *(const float4*)(ArowLo + kn);
            ra1 = *(const float4*)(ArowLo + kn + 4);
            rb0 = *(const float4*)(ArowHi + kn);
            rb1 = *(const float4*)(ArowHi + kn + 4);
            const float4* bsrc = Bp + ((size_t)(i + 1) * nb + blockIdx.x) * 1024 + t * 4;
            float4* bdst = &Bs[(1 - st) * 1024 + t * 4];
            #pragma unroll
            for (int j = 0; j < 4; j++) cp_async16(bdst + j, bsrc + j);
            asm volatile("cp.async.commit_group;");
        }

        const float4* Ast = &As[st * 1024];
        const float4* Bst = &Bs[st * 1024];
        #pragma unroll
        for (int ks = 0; ks < 4; ks++) {
            float4 af0 = Ast[ks * 256 + mt0 * 32 + grp * 4 + (qid ^ ks)];
            float4 af1 = Ast[ks * 256 + mt1 * 32 + grp * 4 + (qid ^ ks)];
            float4 bfp[4];
            #pragma unroll
            for (int p = 0; p < 4; p++) {
                int ntpl = (wn >> 4) + p;
                bfp[p] = Bst[ks * 256 + ntpl * 32 + grp * 4 + qid];
            }
            #pragma unroll
            for (int p = 0; p < 4; p++) {
                mma_tf32(acc[0][2 * p],     &af0.x, &bfp[p].x);
                mma_tf32(acc[0][2 * p + 1], &af0.x, &bfp[p].z);
                mma_tf32(acc[1][2 * p],     &af1.x, &bfp[p].x);
                mma_tf32(acc[1][2 * p + 1], &af1.x, &bfp[p].z);
            }
        }

        if (more) {
            float4* Adst = &As[(1 - st) * 1024];
            const float* qa0 = &ra0.x; const float* qa1 = &ra1.x;
            const float* qb0 = &rb0.x; const float* qb1 = &rb1.x;
            #pragma unroll
            for (int q = 0; q < 4; q++)
                Adst[fa_idx + (q ^ fa_ks)] = make_float4(qa0[q], qb0[q], qa1[q], qb1[q]);
            asm volatile("cp.async.wait_group 0;");
        }
        __syncthreads();
    }

    #pragma unroll
    for (int mt = 0; mt < 2; mt++) {
        const int gr0 = (int)row0 + wm + mt * 16 + grp;
        float s0 = 1.f, s1 = 1.f;
        if (EPI == 3) { s0 = dinv[gr0]; s1 = dinv[gr0 + 8]; }
        #pragma unroll
        for (int nt = 0; nt < 8; nt++) {
            int gc = blockIdx.x * 128 + wn + nt * 8 + 2 * qid;
            float2 v0, v1;
            v0.x = acc[mt][nt][0]; v0.y = acc[mt][nt][1];
            v1.x = acc[mt][nt][2]; v1.y = acc[mt][nt][3];
            if (EPI == 3) { v0.x *= s0; v0.y *= s0; v1.x *= s1; v1.y *= s1; }
            if (EPI == 1 || EPI == 2 || EPI == 4) {
                float bx = bias[gc], by = bias[gc + 1];
                v0.x += bx; v0.y += by; v1.x += bx; v1.y += by;
                if (EPI == 1) {
                    v0.x = to_tf32(fmaxf(v0.x, 0.f)); v0.y = to_tf32(fmaxf(v0.y, 0.f));
                    v1.x = to_tf32(fmaxf(v1.x, 0.f)); v1.y = to_tf32(fmaxf(v1.y, 0.f));
                }
                if (EPI == 4) {
                    float scx = bg[gc]     * rsqrtf(bv[gc]     + BN_EPS);
                    float scy = bg[gc + 1] * rsqrtf(bv[gc + 1] + BN_EPS);
                    float mx = bm[gc], my = bm[gc + 1];
                    float ex = bbe[gc], ey = bbe[gc + 1];
                    v0.x = to_tf32(scx * (fmaxf(v0.x, 0.f) - mx) + ex);
                    v0.y = to_tf32(scy * (fmaxf(v0.y, 0.f) - my) + ey);
                    v1.x = to_tf32(scx * (fmaxf(v1.x, 0.f) - mx) + ex);
                    v1.y = to_tf32(scy * (fmaxf(v1.y, 0.f) - my) + ey);
                }
            }
            *(float2*)(C + (size_t)gr0 * Nd + gc)       = v0;
            *(float2*)(C + (size_t)(gr0 + 8) * Nd + gc) = v1;
        }
    }
}

// ---------------- layer-1 input aggregation (dinv fused inline) ----------------
// agg[n] = tf32( dinv[n] * ( dinv[n]*x[n] + sum_s dinv[s]*x[s] ) )
__global__ __launch_bounds__(256) void gather_agg_k(
    const int* __restrict__ offs, const int* __restrict__ eidx,
    const float* __restrict__ x, const float* __restrict__ dinv,
    float* __restrict__ agg)
{
    int node = blockIdx.x * 8 + (threadIdx.x >> 5);
    int lane = threadIdx.x & 31;
    if (node >= Nn) return;

    float dvn = dinv[node];
    float4 xv = ((const float4*)(x + (size_t)node * DIN))[lane];
    float4 acc;
    acc.x = xv.x * dvn; acc.y = xv.y * dvn; acc.z = xv.z * dvn; acc.w = xv.w * dvn;

    int lo = offs[node], hi = offs[node + 1];
    for (int e = lo; e < hi; e++) {
        int s = eidx[e];
        float ds = dinv[s];
        float4 t = ((const float4*)(x + (size_t)s * DIN))[lane];
        acc.x += t.x * ds; acc.y += t.y * ds; acc.z += t.z * ds; acc.w += t.w * ds;
    }
    acc.x = to_tf32(dvn * acc.x); acc.y = to_tf32(dvn * acc.y);
    acc.z = to_tf32(dvn * acc.z); acc.w = to_tf32(dvn * acc.w);
    ((float4*)(agg + (size_t)node * DIN))[lane] = acc;
}

// ---------------- column-split fused gather + bias + relu + BN ----------------
// grid (Nn/8, Nd/128): each block = 8 nodes x 128 columns (1 float4/lane).
// Column slice footprint of hs = Nn*128*4 = 64MB -> L2-resident.
template <bool CVT>
__global__ __launch_bounds__(256) void gather_bn_k(
    const int* __restrict__ offs, const int* __restrict__ eidx,
    const float* __restrict__ hs, const float* __restrict__ dinv,
    const float* __restrict__ b,
    const float* __restrict__ g, const float* __restrict__ be,
    const float* __restrict__ m, const float* __restrict__ v,
    float* __restrict__ act, int Nd)
{
    int node = blockIdx.x * 8 + (threadIdx.x >> 5);
    int lane = threadIdx.x & 31;
    if (node >= Nn) return;
    const int q = Nd >> 2;                    // float4s per row
    const int c4 = (blockIdx.y << 5) + lane;  // float4 index within row

    float4 acc = ((const float4*)(hs + (size_t)node * Nd))[c4];

    int lo = offs[node], hi = offs[node + 1];
    for (int e = lo; e < hi; e++) {
        int s = eidx[e];
        float4 t = ((const float4*)hs)[(size_t)s * q + c4];
        acc.x += t.x; acc.y += t.y; acc.z += t.z; acc.w += t.w;
    }

    float dv = dinv[node];
    int c = c4 * 4;
    float4 bb = *(const float4*)(b + c);
    float4 gg = *(const float4*)(g + c);
    float4 eb = *(const float4*)(be + c);
    float4 mm = *(const float4*)(m + c);
    float4 vv = *(const float4*)(v + c);
    float4 r;
    float y;
    y = fmaxf(dv * acc.x + bb.x, 0.f);
    r.x = gg.x * rsqrtf(vv.x + BN_EPS) * (y - mm.x) + eb.x;
    y = fmaxf(dv * acc.y + bb.y, 0.f);
    r.y = gg.y * rsqrtf(vv.y + BN_EPS) * (y - mm.y) + eb.y;
    y = fmaxf(dv * acc.z + bb.z, 0.f);
    r.z = gg.z * rsqrtf(vv.z + BN_EPS) * (y - mm.z) + eb.z;
    y = fmaxf(dv * acc.w + bb.w, 0.f);
    r.w = gg.w * rsqrtf(vv.w + BN_EPS) * (y - mm.w) + eb.w;
    if (CVT) {
        r.x = to_tf32(r.x); r.y = to_tf32(r.y);
        r.z = to_tf32(r.z); r.w = to_tf32(r.w);
    }
    ((float4*)(act + (size_t)node * Nd))[c4] = r;
}

// ---------------- mean pool ----------------
__device__ __forceinline__ int lower_bound_i(const int* a, int n, int key) {
    int lo = 0, hi = n;
    while (lo < hi) { int mid = (lo + hi) >> 1; if (a[mid] < key) lo = mid + 1; else hi = mid; }
    return lo;
}
__global__ void pool_k(const float* __restrict__ h, const int* __restrict__ batch,
                       float* __restrict__ pooled)
{
    int gph = blockIdx.x;
    __shared__ int s_lo, s_hi;
    if (threadIdx.x == 0) {
        s_lo = lower_bound_i(batch, Nn, gph);
        s_hi = lower_bound_i(batch, Nn, gph + 1);
    }
    __syncthreads();
    int lo = s_lo, hi = s_hi;
    int c = threadIdx.x;
    float acc = 0.f;
    for (int i = lo; i < hi; i++) acc += h[(size_t)i * DOUT + c];
    float cnt = (float)((hi - lo) > 0 ? (hi - lo) : 1);
    pooled[gph * DOUT + c] = to_tf32(acc / cnt);
}

// ---------------- launch ----------------
extern "C" void kernel_launch(void* const* d_in, const int* in_sizes, int n_in,
                              void* d_out, int out_size)
{
    const float* x   = (const float*)d_in[0];
    const int*   ei  = (const int*)  d_in[1];
    const int*   bat = (const int*)  d_in[2];
    const float* W1  = (const float*)d_in[3];
    const float* b1  = (const float*)d_in[4];
    const float* W2  = (const float*)d_in[5];
    const float* b2  = (const float*)d_in[6];
    const float* W3  = (const float*)d_in[7];
    const float* b3  = (const float*)d_in[8];
    const float* g1  = (const float*)d_in[9];
    const float* be1 = (const float*)d_in[10];
    const float* m1  = (const float*)d_in[11];
    const float* v1  = (const float*)d_in[12];
    const float* g2  = (const float*)d_in[13];
    const float* be2 = (const float*)d_in[14];
    const float* m2  = (const float*)d_in[15];
    const float* v2  = (const float*)d_in[16];
    const float* g3  = (const float*)d_in[17];
    const float* be3 = (const float*)d_in[18];
    const float* m3  = (const float*)d_in[19];
    const float* v3  = (const float*)d_in[20];
    const float* Wf1 = (const float*)d_in[21];
    const float* bf1 = (const float*)d_in[22];
    const float* Wf2 = (const float*)d_in[23];
    const float* bf2 = (const float*)d_in[24];

    const int* src = ei;
    const int* dst = ei + Ee;

    float *p_deg, *p_dinv, *p_hs, *p_act, *p_pool, *p_tmp;
    float4* p_bp;
    int *p_edeg, *p_offs, *p_cur, *p_eidx, *p_part;
    cudaGetSymbolAddress((void**)&p_deg,  g_deg);
    cudaGetSymbolAddress((void**)&p_dinv, g_dinv);
    cudaGetSymbolAddress((void**)&p_hs,   g_hs);
    cudaGetSymbolAddress((void**)&p_act,  g_act);
    cudaGetSymbolAddress((void**)&p_pool, g_pool);
    cudaGetSymbolAddress((void**)&p_tmp,  g_tmp);
    cudaGetSymbolAddress((void**)&p_bp,   g_bpack);
    cudaGetSymbolAddress((void**)&p_edeg, g_edeg);
    cudaGetSymbolAddress((void**)&p_offs, g_offs);
    cudaGetSymbolAddress((void**)&p_cur,  g_cur);
    cudaGetSymbolAddress((void**)&p_eidx, g_eidx);
    cudaGetSymbolAddress((void**)&p_part, g_part);

    const int SMEM = 65536;
    cudaFuncSetAttribute(tgemm_k<1>, cudaFuncAttributeMaxDynamicSharedMemorySize, SMEM);
    cudaFuncSetAttribute(tgemm_k<2>, cudaFuncAttributeMaxDynamicSharedMemorySize, SMEM);
    cudaFuncSetAttribute(tgemm_k<3>, cudaFuncAttributeMaxDynamicSharedMemorySize, SMEM);
    cudaFuncSetAttribute(tgemm_k<4>, cudaFuncAttributeMaxDynamicSharedMemorySize, SMEM);

    // degree / dinv / CSR
    deg_init_k<<<Nn / 256, 256>>>(p_deg, p_edeg);
    deg_acc_k <<<Ee / 256, 256>>>(dst, p_deg, p_edeg);
    dinv_k    <<<Nn / 256, 256>>>(p_deg, p_dinv);
    scan1_k<<<256, 512>>>(p_edeg, p_offs, p_part);
    scan2_k<<<1, 256>>>(p_part);
    scan3_k<<<Nn / 256, 256>>>(p_offs, p_cur, p_part);
    fill_k <<<Ee / 256, 256>>>(src, dst, p_cur, p_eidx);

    // ---- layer 1: aggregate-then-GEMM (Âx)W1 with fused BN epilogue ----
    gather_agg_k<<<Nn / 8, 256>>>(p_offs, p_eidx, x, p_dinv, p_hs);
    packB_k<<<(DIN/32)*(DH/128)*1024/256, 256>>>(W1, p_bp, DIN, DH);
    tgemm_k<4><<<dim3(DH/128, Nn/128), 256, SMEM>>>(p_hs, p_bp, b1, nullptr, g1, be1, m1, v1, p_act, Nn, DIN, DH);

    // ---- layer 2 ----
    packB_k<<<(DH/32)*(DH/128)*1024/256, 256>>>(W2, p_bp, DH, DH);
    tgemm_k<3><<<dim3(DH/128, Nn/128), 256, SMEM>>>(p_act, p_bp, nullptr, p_dinv, nullptr, nullptr, nullptr, nullptr, p_hs, Nn, DH, DH);
    gather_bn_k<true><<<dim3(Nn / 8, DH / 128), 256>>>(p_offs, p_eidx, p_hs, p_dinv, b2, g2, be2, m2, v2, p_act, DH);

    // ---- layer 3 ----
    packB_k<<<(DH/32)*(DOUT/128)*1024/256, 256>>>(W3, p_bp, DH, DOUT);
    tgemm_k<3><<<dim3(DOUT/128, Nn/128), 256, SMEM>>>(p_act, p_bp, nullptr, p_dinv, nullptr, nullptr, nullptr, nullptr, p_hs, Nn, DH, DOUT);
    gather_bn_k<false><<<dim3(Nn / 8, DOUT / 128), 256>>>(p_offs, p_eidx, p_hs, p_dinv, b3, g3, be3, m3, v3, p_act, DOUT);

    // ---- pool + MLP head ----
    pool_k<<<Gg, DOUT>>>(p_act, bat, p_pool);
    packB_k<<<(DOUT/32)*(DOUT/128)*1024/256, 256>>>(Wf1, p_bp, DOUT, DOUT);
    tgemm_k<1><<<dim3(DOUT/128, Gg/128), 256, SMEM>>>(p_pool, p_bp, bf1, nullptr, nullptr, nullptr, nullptr, nullptr, p_tmp, Gg, DOUT, DOUT);
    packB_k<<<(DOUT/32)*(DOUT/128)*1024/256, 256>>>(Wf2, p_bp, DOUT, DOUT);
    tgemm_k<2><<<dim3(DOUT/128, Gg/128), 256, SMEM>>>(p_tmp, p_bp, bf2, nullptr, nullptr, nullptr, nullptr, nullptr, (float*)d_out, Gg, DOUT, DOUT);
}